// round 1
// baseline (speedup 1.0000x reference)
#include <cuda_runtime.h>
#include <cstdint>
#include <cstddef>

#define IN 2048
#define DIM 128
#define NBATCH 4
#define ITERS 50
#define KELEMS (NBATCH*IN*IN)   // 16,777,216 floats = 67 MB

// ---------------- scratch (static device globals: allocation-free) ----------
__device__ float g_K1[KELEMS];                 // K for OT1 (src,tgt)
__device__ float g_K2[KELEMS];                 // K for OT2 (tgt,gen)
__device__ float g_A[2][3][NBATCH*IN];         // triple-buffered column accumulators
__device__ float g_u[2][NBATCH*IN];            // final u per OT
__device__ float g_vfin[2][NBATCH*IN];         // final v per OT
__device__ unsigned g_bar;                     // grid barrier counter

// exp(1 - c) for c in [-1,1]; degree-9 Taylor around 0 of exp(t), t=-c, times e.
// Max rel error ~1e-7 on the range. Pure FFMA: avoids MUFU bottleneck.
__device__ __forceinline__ float exp_shift(float c){
    float t = -c;
    float p = 2.7557319e-6f;          // 1/9!
    p = fmaf(p, t, 2.4801587e-5f);    // 1/8!
    p = fmaf(p, t, 1.9841270e-4f);    // 1/7!
    p = fmaf(p, t, 1.3888889e-3f);    // 1/6!
    p = fmaf(p, t, 8.3333333e-3f);    // 1/5!
    p = fmaf(p, t, 4.1666667e-2f);    // 1/4!
    p = fmaf(p, t, 1.6666667e-1f);    // 1/3!
    p = fmaf(p, t, 0.5f);
    p = fmaf(p, t, 1.0f);
    p = fmaf(p, t, 1.0f);
    return 2.7182818284f * p;
}

// ---------------- init: zero barrier + output, set sinkhorn buffers --------
__global__ void init_kernel(float* out){
    int idx = blockIdx.x * blockDim.x + threadIdx.x;
    if (idx == 0){ g_bar = 0u; out[0] = 0.0f; }
    if (idx < NBATCH*IN){
        g_A[0][0][idx] = 1.0f;   // epoch 0 reads buf0 => v = 1/1 = ones
        g_A[1][0][idx] = 1.0f;
        g_A[0][1][idx] = 0.0f;   // epoch 0 accumulates into buf1
        g_A[1][1][idx] = 0.0f;
    }
}

// ---------------- GEMM + exp: K[b][i][o] = exp(1 - q_i . k_o), diag=e^-10 ---
#define BM 128
#define BN 128
#define DC 32

__global__ __launch_bounds__(256) void gemm_exp_kernel(
        const float* __restrict__ src, const float* __restrict__ tgt,
        const float* __restrict__ gen){
    int ot = blockIdx.z >> 2;
    int b  = blockIdx.z & 3;
    const float* q  = (ot ? tgt : src) + (size_t)b * IN * DIM;
    const float* kk = (ot ? gen : tgt) + (size_t)b * IN * DIM;
    float* Kout     = (ot ? g_K2 : g_K1) + (size_t)b * IN * IN;
    int i0 = blockIdx.y * BM;
    int o0 = blockIdx.x * BN;

    __shared__ float As[DC][BM + 4];   // transposed: As[d][row]
    __shared__ float Bs[DC][BN + 4];

    int tid = threadIdx.x;
    int tx = tid & 15, ty = tid >> 4;
    float c[8][8] = {};

    for (int dc = 0; dc < DIM; dc += DC){
        #pragma unroll
        for (int l = 0; l < 4; l++){
            int fidx = tid + 256 * l;          // 0..1023 = 128 rows x 8 float4
            int r  = fidx >> 3;
            int d4 = (fidx & 7) << 2;
            float4 va = *(const float4*)(q  + (size_t)(i0 + r) * DIM + dc + d4);
            float4 vb = *(const float4*)(kk + (size_t)(o0 + r) * DIM + dc + d4);
            As[d4+0][r] = va.x; As[d4+1][r] = va.y; As[d4+2][r] = va.z; As[d4+3][r] = va.w;
            Bs[d4+0][r] = vb.x; Bs[d4+1][r] = vb.y; Bs[d4+2][r] = vb.z; Bs[d4+3][r] = vb.w;
        }
        __syncthreads();
        #pragma unroll
        for (int d = 0; d < DC; d++){
            float a[8], bb[8];
            #pragma unroll
            for (int i = 0; i < 8; i++) a[i]  = As[d][ty*8 + i];
            #pragma unroll
            for (int j = 0; j < 8; j++) bb[j] = Bs[d][tx*8 + j];
            #pragma unroll
            for (int i = 0; i < 8; i++)
                #pragma unroll
                for (int j = 0; j < 8; j++)
                    c[i][j] = fmaf(a[i], bb[j], c[i][j]);
        }
        __syncthreads();
    }

    #pragma unroll
    for (int i = 0; i < 8; i++){
        int gi = i0 + ty*8 + i;
        #pragma unroll
        for (int j4 = 0; j4 < 8; j4 += 4){
            int go = o0 + tx*8 + j4;
            float4 v;
            v.x = (gi == go + 0) ? 4.5399930e-5f : exp_shift(c[i][j4+0]);
            v.y = (gi == go + 1) ? 4.5399930e-5f : exp_shift(c[i][j4+1]);
            v.z = (gi == go + 2) ? 4.5399930e-5f : exp_shift(c[i][j4+2]);
            v.w = (gi == go + 3) ? 4.5399930e-5f : exp_shift(c[i][j4+3]);
            *(float4*)(Kout + (size_t)gi * IN + go) = v;
        }
    }
}

// ---------------- persistent fused Sinkhorn ---------------------------------
// Per epoch e (per OT): v = 1/A_e (buf e%3); for each row: u = 1/(K v), and
// accumulate K^T u into buf (e+1)%3 (atomics); zero buf (e+2)%3 for next epoch.
// One grid barrier per epoch. OTs run sequentially so K (67MB) stays L2-resident.
__global__ __launch_bounds__(512, 1) void sinkhorn_kernel(int nblocks){
    __shared__ __align__(16) float v_sh[IN];
    __shared__ float u_sh[16];
    int tid  = threadIdx.x;
    int lane = tid & 31, warp = tid >> 5;

    int seg = blockIdx.x & 3;                       // batch segment 0..3
    int bis = blockIdx.x >> 2;                      // block index within segment
    int nbs = (nblocks - seg + 3) >> 2;             // blocks in this segment
    int r0 = (int)(((long)IN * bis) / nbs);
    int r1 = (int)(((long)IN * (bis + 1)) / nbs);

    unsigned barcnt = 0;
    for (int ot = 0; ot < 2; ot++){
        const float* Kb = (ot ? g_K2 : g_K1) + (size_t)seg * IN * IN;
        const float4* Kb4 = (const float4*)Kb;
        for (int e = 0; e < ITERS; e++){
            const float* Ar = &g_A[ot][e % 3][seg * IN];
            float*       Az = &g_A[ot][(e + 2) % 3][seg * IN];
            for (int o = tid; o < IN; o += 512){
                v_sh[o] = 1.0f / __ldcg(Ar + o);    // L2 read (cross-barrier data)
                Az[o] = 0.0f;                        // idempotent zero for next epoch
            }
            __syncthreads();

            float4 acc = make_float4(0.f, 0.f, 0.f, 0.f);
            for (int tb = r0; tb < r1; tb += 16){
                int nrow = min(16, r1 - tb);
                // phase A: warp w owns row tb+w; dot with v, u = 1/dot
                if (warp < nrow){
                    int row = tb + warp;
                    const float4* Kr = (const float4*)(Kb + (size_t)row * IN);
                    const float4* V4 = (const float4*)v_sh;
                    float dx = 0.f, dy = 0.f, dz = 0.f, dw = 0.f;
                    #pragma unroll
                    for (int j = 0; j < 16; j++){
                        float4 kv = Kr[j * 32 + lane];
                        float4 vv = V4[j * 32 + lane];
                        dx = fmaf(kv.x, vv.x, dx);
                        dy = fmaf(kv.y, vv.y, dy);
                        dz = fmaf(kv.z, vv.z, dz);
                        dw = fmaf(kv.w, vv.w, dw);
                    }
                    float dot = (dx + dy) + (dz + dw);
                    #pragma unroll
                    for (int off = 16; off; off >>= 1)
                        dot += __shfl_xor_sync(0xffffffffu, dot, off);
                    float u = 1.0f / dot;
                    if (lane == 0){
                        u_sh[warp] = u;
                        g_u[ot][seg * IN + row] = u;
                    }
                }
                __syncthreads();
                // phase B: warp w owns column slab [w*128, w*128+128); rows L1-hot
                const float4* Ks = Kb4 + (size_t)tb * (IN/4) + warp * 32 + lane;
                if (nrow == 16){
                    #pragma unroll
                    for (int r = 0; r < 16; r++){
                        float4 kv = Ks[(size_t)r * (IN/4)];
                        float u = u_sh[r];
                        acc.x = fmaf(u, kv.x, acc.x);
                        acc.y = fmaf(u, kv.y, acc.y);
                        acc.z = fmaf(u, kv.z, acc.z);
                        acc.w = fmaf(u, kv.w, acc.w);
                    }
                } else {
                    for (int r = 0; r < nrow; r++){
                        float4 kv = Ks[(size_t)r * (IN/4)];
                        float u = u_sh[r];
                        acc.x = fmaf(u, kv.x, acc.x);
                        acc.y = fmaf(u, kv.y, acc.y);
                        acc.z = fmaf(u, kv.z, acc.z);
                        acc.w = fmaf(u, kv.w, acc.w);
                    }
                }
                __syncthreads();
            }
            // flush column partials (each block touches each column exactly once)
            float* Aw = &g_A[ot][(e + 1) % 3][seg * IN];
            int col = warp * 128 + lane * 4;
            atomicAdd(Aw + col + 0, acc.x);
            atomicAdd(Aw + col + 1, acc.y);
            atomicAdd(Aw + col + 2, acc.z);
            atomicAdd(Aw + col + 3, acc.w);

            // grid barrier
            __threadfence();
            __syncthreads();
            barcnt++;
            if (tid == 0){
                atomicAdd(&g_bar, 1u);
                volatile unsigned* vb = &g_bar;
                unsigned target = barcnt * (unsigned)nblocks;
                while (*vb < target) { }
            }
            __syncthreads();
        }
    }
}

// ---------------- finalize v = 1/A_final ------------------------------------
__global__ void vfin_kernel(){
    int idx = blockIdx.x * blockDim.x + threadIdx.x;
    if (idx < 2 * NBATCH * IN){
        int ot = idx / (NBATCH * IN);
        int r  = idx % (NBATCH * IN);
        g_vfin[ot][r] = 1.0f / g_A[ot][ITERS % 3][r];   // A_50 lives in buf 50%3
    }
}

// ---------------- loss: mean |u1 K1 v1 - u2 K2 v2| --------------------------
__global__ __launch_bounds__(256) void loss_kernel(float* __restrict__ out){
    const float4* K1 = (const float4*)g_K1;
    const float4* K2 = (const float4*)g_K2;
    const float4* V1 = (const float4*)g_vfin[0];
    const float4* V2 = (const float4*)g_vfin[1];
    int total = KELEMS / 4;
    float s = 0.f;
    for (int idx = blockIdx.x * blockDim.x + threadIdx.x; idx < total;
         idx += gridDim.x * blockDim.x){
        int o4 = idx & 511;
        int t  = idx >> 9;
        int i  = t & 2047;
        int b  = t >> 11;
        int row = b * IN + i;
        float u1 = g_u[0][row], u2 = g_u[1][row];
        float4 k1 = K1[idx], k2 = K2[idx];
        float4 v1 = V1[b * 512 + o4], v2 = V2[b * 512 + o4];
        s += fabsf(u1 * k1.x * v1.x - u2 * k2.x * v2.x);
        s += fabsf(u1 * k1.y * v1.y - u2 * k2.y * v2.y);
        s += fabsf(u1 * k1.z * v1.z - u2 * k2.z * v2.z);
        s += fabsf(u1 * k1.w * v1.w - u2 * k2.w * v2.w);
    }
    __shared__ float red[256];
    red[threadIdx.x] = s;
    __syncthreads();
    for (int st = 128; st; st >>= 1){
        if (threadIdx.x < st) red[threadIdx.x] += red[threadIdx.x + st];
        __syncthreads();
    }
    if (threadIdx.x == 0) atomicAdd(out, red[0] * (1.0f / 16777216.0f));
}

// ---------------- launch ----------------------------------------------------
extern "C" void kernel_launch(void* const* d_in, const int* in_sizes, int n_in,
                              void* d_out, int out_size){
    const float* src = (const float*)d_in[0];
    const float* tgt = (const float*)d_in[1];
    const float* gen = (const float*)d_in[2];
    float* out = (float*)d_out;

    int dev = 0;
    cudaGetDevice(&dev);
    int sm = 148;
    cudaDeviceGetAttribute(&sm, cudaDevAttrMultiProcessorCount, dev);

    init_kernel<<<32, 256>>>(out);
    dim3 ggrid(IN / BN, IN / BM, 8);          // (o-tile, i-tile, ot*4+b)
    gemm_exp_kernel<<<ggrid, 256>>>(src, tgt, gen);
    sinkhorn_kernel<<<sm, 512>>>(sm);
    vfin_kernel<<<16, 1024>>>();
    loss_kernel<<<2048, 256>>>(out);
}

// round 3
// speedup vs baseline: 1.3592x; 1.3592x over previous
#include <cuda_runtime.h>
#include <cuda_fp16.h>
#include <cstdint>
#include <cstddef>

#define IN 2048
#define DIM 128
#define NBATCH 4
#define ITERS 50
#define KELEMS (NBATCH*IN*IN)   // 16,777,216 elements

// ---------------- scratch (static device globals: allocation-free) ----------
__device__ __half g_K1[KELEMS];                // K for OT1 (src,tgt)  33.5 MB
__device__ __half g_K2[KELEMS];                // K for OT2 (tgt,gen)  33.5 MB
__device__ float g_A[2][3][NBATCH*IN];         // triple-buffered column accumulators
__device__ float g_u[2][NBATCH*IN];            // final u per OT
__device__ float g_vfin[2][NBATCH*IN];         // final v per OT
__device__ unsigned g_bar;                     // grid barrier counter

// exp(1 - c) for c in [-1,1]; degree-9 Taylor of exp(t), t=-c, times e.
// Max rel error ~1e-7 on the range. Pure FFMA: avoids MUFU bottleneck.
__device__ __forceinline__ float exp_shift(float c){
    float t = -c;
    float p = 2.7557319e-6f;
    p = fmaf(p, t, 2.4801587e-5f);
    p = fmaf(p, t, 1.9841270e-4f);
    p = fmaf(p, t, 1.3888889e-3f);
    p = fmaf(p, t, 8.3333333e-3f);
    p = fmaf(p, t, 4.1666667e-2f);
    p = fmaf(p, t, 1.6666667e-1f);
    p = fmaf(p, t, 0.5f);
    p = fmaf(p, t, 1.0f);
    p = fmaf(p, t, 1.0f);
    return 2.7182818284f * p;
}

// ---------------- init ------------------------------------------------------
__global__ void init_kernel(float* out){
    int idx = blockIdx.x * blockDim.x + threadIdx.x;
    if (idx == 0){ g_bar = 0u; out[0] = 0.0f; }
    if (idx < NBATCH*IN){
        g_A[0][0][idx] = 1.0f;   // epoch 0 reads buf0 => v = ones
        g_A[1][0][idx] = 1.0f;
        g_A[0][1][idx] = 0.0f;   // epoch 0 accumulates into buf1
        g_A[1][1][idx] = 0.0f;
        g_A[0][2][idx] = 0.0f;
        g_A[1][2][idx] = 0.0f;
    }
}

// ---------------- GEMM + exp -> fp16 K --------------------------------------
#define BM 128
#define BN 128
#define DC 32

__global__ __launch_bounds__(256) void gemm_exp_kernel(
        const float* __restrict__ src, const float* __restrict__ tgt,
        const float* __restrict__ gen){
    int ot = blockIdx.z >> 2;
    int b  = blockIdx.z & 3;
    const float* q  = (ot ? tgt : src) + (size_t)b * IN * DIM;
    const float* kk = (ot ? gen : tgt) + (size_t)b * IN * DIM;
    __half* Kout    = (ot ? g_K2 : g_K1) + (size_t)b * IN * IN;
    int i0 = blockIdx.y * BM;
    int o0 = blockIdx.x * BN;

    __shared__ float As[DC][BM + 4];
    __shared__ float Bs[DC][BN + 4];

    int tid = threadIdx.x;
    int tx = tid & 15, ty = tid >> 4;
    float c[8][8] = {};

    for (int dc = 0; dc < DIM; dc += DC){
        #pragma unroll
        for (int l = 0; l < 4; l++){
            int fidx = tid + 256 * l;
            int r  = fidx >> 3;
            int d4 = (fidx & 7) << 2;
            float4 va = *(const float4*)(q  + (size_t)(i0 + r) * DIM + dc + d4);
            float4 vb = *(const float4*)(kk + (size_t)(o0 + r) * DIM + dc + d4);
            As[d4+0][r] = va.x; As[d4+1][r] = va.y; As[d4+2][r] = va.z; As[d4+3][r] = va.w;
            Bs[d4+0][r] = vb.x; Bs[d4+1][r] = vb.y; Bs[d4+2][r] = vb.z; Bs[d4+3][r] = vb.w;
        }
        __syncthreads();
        #pragma unroll
        for (int d = 0; d < DC; d++){
            float a[8], bb[8];
            #pragma unroll
            for (int i = 0; i < 8; i++) a[i]  = As[d][ty*8 + i];
            #pragma unroll
            for (int j = 0; j < 8; j++) bb[j] = Bs[d][tx*8 + j];
            #pragma unroll
            for (int i = 0; i < 8; i++)
                #pragma unroll
                for (int j = 0; j < 8; j++)
                    c[i][j] = fmaf(a[i], bb[j], c[i][j]);
        }
        __syncthreads();
    }

    #pragma unroll
    for (int i = 0; i < 8; i++){
        int gi = i0 + ty*8 + i;
        int gc = o0 + tx*8;
        __half2 h[4];
        #pragma unroll
        for (int j2 = 0; j2 < 4; j2++){
            int go = gc + j2*2;
            float fx = (gi == go + 0) ? 4.5399930e-5f : exp_shift(c[i][j2*2+0]);
            float fy = (gi == go + 1) ? 4.5399930e-5f : exp_shift(c[i][j2*2+1]);
            h[j2] = __floats2half2_rn(fx, fy);
        }
        *(uint4*)(Kout + (size_t)gi * IN + gc) = *(uint4*)h;
    }
}

// ---------------- persistent fused Sinkhorn (fp16 K, both OTs per barrier) --
__global__ __launch_bounds__(512, 1) void sinkhorn_kernel(int nblocks){
    __shared__ __align__(16) __half2 v_sh[IN/2];   // 4 KB
    __shared__ __half2 u_sh[16];
    int tid  = threadIdx.x;
    int lane = tid & 31, warp = tid >> 5;

    int seg = blockIdx.x & 3;                       // batch segment 0..3
    int bis = blockIdx.x >> 2;
    int nbs = (nblocks - seg + 3) >> 2;
    int r0 = (int)(((long)IN * bis) / nbs);
    int r1 = (int)(((long)IN * (bis + 1)) / nbs);

    unsigned barcnt = 0;
    for (int e = 0; e < ITERS; e++){
        for (int ot = 0; ot < 2; ot++){
            const __half* Kb = (ot ? g_K2 : g_K1) + (size_t)seg * IN * IN;
            const float* Ar = &g_A[ot][e % 3][seg * IN];
            float*       Az = &g_A[ot][(e + 2) % 3][seg * IN];
            for (int o = tid; o < IN; o += 512){
                float v = 1.0f / __ldcg(Ar + o);
                ((__half*)v_sh)[o] = __float2half_rn(v);
                Az[o] = 0.0f;                        // idempotent zero for next epoch
            }
            __syncthreads();

            float2 accf0 = make_float2(0.f, 0.f);    // this lane's 4 column sums
            float2 accf1 = make_float2(0.f, 0.f);
            for (int tb = r0; tb < r1; tb += 16){
                int nrow = min(16, r1 - tb);
                // phase A: warp w owns row tb+w: u = 1/(K v) via half2 tree
                if (warp < nrow){
                    int row = tb + warp;
                    const uint4* Kr = (const uint4*)(Kb + (size_t)row * IN);
                    const uint4* V4 = (const uint4*)v_sh;
                    float ax = 0.f, ay = 0.f;
                    #pragma unroll
                    for (int j = 0; j < 8; j++){
                        uint4 kv = Kr[j * 32 + lane];
                        uint4 vv = V4[j * 32 + lane];
                        __half2 p0 = __hmul2(*(__half2*)&kv.x, *(__half2*)&vv.x);
                        __half2 p1 = __hmul2(*(__half2*)&kv.y, *(__half2*)&vv.y);
                        __half2 p2 = __hmul2(*(__half2*)&kv.z, *(__half2*)&vv.z);
                        __half2 p3 = __hmul2(*(__half2*)&kv.w, *(__half2*)&vv.w);
                        __half2 s  = __hadd2(__hadd2(p0, p1), __hadd2(p2, p3));
                        float2 f = __half22float2(s);
                        ax += f.x; ay += f.y;
                    }
                    float dot = ax + ay;
                    #pragma unroll
                    for (int off = 16; off; off >>= 1)
                        dot += __shfl_xor_sync(0xffffffffu, dot, off);
                    float u = 1.0f / dot;
                    if (lane == 0){
                        u_sh[warp] = __half2half2(__float2half_rn(u));
                        g_u[ot][seg * IN + row] = u;
                    }
                }
                __syncthreads();
                // phase B: lane owns 4 columns; rows L1-hot from phase A
                const uint2* Ks = (const uint2*)(Kb + (size_t)tb * IN + warp * 128 + lane * 4);
                __half2 h0 = __float2half2_rn(0.f);
                __half2 h1 = __float2half2_rn(0.f);
                if (nrow == 16){
                    #pragma unroll
                    for (int r = 0; r < 16; r++){
                        uint2 kv = Ks[(size_t)r * (IN/4)];
                        __half2 u2 = u_sh[r];
                        h0 = __hfma2(u2, *(__half2*)&kv.x, h0);
                        h1 = __hfma2(u2, *(__half2*)&kv.y, h1);
                    }
                } else {
                    for (int r = 0; r < nrow; r++){
                        uint2 kv = Ks[(size_t)r * (IN/4)];
                        __half2 u2 = u_sh[r];
                        h0 = __hfma2(u2, *(__half2*)&kv.x, h0);
                        h1 = __hfma2(u2, *(__half2*)&kv.y, h1);
                    }
                }
                float2 f0 = __half22float2(h0);
                float2 f1 = __half22float2(h1);
                accf0.x += f0.x; accf0.y += f0.y;
                accf1.x += f1.x; accf1.y += f1.y;
                __syncthreads();
            }
            // flush column partials
            float* Aw = &g_A[ot][(e + 1) % 3][seg * IN];
            int col = warp * 128 + lane * 4;
            atomicAdd(Aw + col + 0, accf0.x);
            atomicAdd(Aw + col + 1, accf0.y);
            atomicAdd(Aw + col + 2, accf1.x);
            atomicAdd(Aw + col + 3, accf1.y);
            __syncthreads();
        }

        // one grid barrier per epoch (covers both OTs)
        __threadfence();
        __syncthreads();
        barcnt++;
        if (tid == 0){
            atomicAdd(&g_bar, 1u);
            volatile unsigned* vb = &g_bar;
            unsigned target = barcnt * (unsigned)nblocks;
            while (*vb < target) { __nanosleep(64); }
        }
        __syncthreads();
    }
}

// ---------------- finalize v = 1/A_final ------------------------------------
__global__ void vfin_kernel(){
    int idx = blockIdx.x * blockDim.x + threadIdx.x;
    if (idx < 2 * NBATCH * IN){
        int ot = idx / (NBATCH * IN);
        int r  = idx % (NBATCH * IN);
        g_vfin[ot][r] = 1.0f / g_A[ot][ITERS % 3][r];
    }
}

// ---------------- loss: mean |u1 K1 v1 - u2 K2 v2| --------------------------
__global__ __launch_bounds__(256) void loss_kernel(float* __restrict__ out){
    const uint4* K1 = (const uint4*)g_K1;
    const uint4* K2 = (const uint4*)g_K2;
    const float4* V1 = (const float4*)g_vfin[0];
    const float4* V2 = (const float4*)g_vfin[1];
    int total = KELEMS / 8;
    float s = 0.f;
    for (int idx = blockIdx.x * blockDim.x + threadIdx.x; idx < total;
         idx += gridDim.x * blockDim.x){
        int o8 = idx & 255;          // uint4 (8 halves) within row
        int t  = idx >> 8;
        int i  = t & 2047;
        int b  = t >> 11;
        int row = b * IN + i;
        float u1 = g_u[0][row], u2 = g_u[1][row];
        uint4 k1 = K1[idx], k2 = K2[idx];
        float4 v1a = V1[b * 512 + o8 * 2], v1b = V1[b * 512 + o8 * 2 + 1];
        float4 v2a = V2[b * 512 + o8 * 2], v2b = V2[b * 512 + o8 * 2 + 1];
        float2 a0 = __half22float2(*(__half2*)&k1.x);
        float2 a1 = __half22float2(*(__half2*)&k1.y);
        float2 a2 = __half22float2(*(__half2*)&k1.z);
        float2 a3 = __half22float2(*(__half2*)&k1.w);
        float2 b0 = __half22float2(*(__half2*)&k2.x);
        float2 b1 = __half22float2(*(__half2*)&k2.y);
        float2 b2 = __half22float2(*(__half2*)&k2.z);
        float2 b3 = __half22float2(*(__half2*)&k2.w);
        s += fabsf(u1 * a0.x * v1a.x - u2 * b0.x * v2a.x);
        s += fabsf(u1 * a0.y * v1a.y - u2 * b0.y * v2a.y);
        s += fabsf(u1 * a1.x * v1a.z - u2 * b1.x * v2a.z);
        s += fabsf(u1 * a1.y * v1a.w - u2 * b1.y * v2a.w);
        s += fabsf(u1 * a2.x * v1b.x - u2 * b2.x * v2b.x);
        s += fabsf(u1 * a2.y * v1b.y - u2 * b2.y * v2b.y);
        s += fabsf(u1 * a3.x * v1b.z - u2 * b3.x * v2b.z);
        s += fabsf(u1 * a3.y * v1b.w - u2 * b3.y * v2b.w);
    }
    __shared__ float red[256];
    red[threadIdx.x] = s;
    __syncthreads();
    for (int st = 128; st; st >>= 1){
        if (threadIdx.x < st) red[threadIdx.x] += red[threadIdx.x + st];
        __syncthreads();
    }
    if (threadIdx.x == 0) atomicAdd(out, red[0] * (1.0f / 16777216.0f));
}

// ---------------- launch ----------------------------------------------------
extern "C" void kernel_launch(void* const* d_in, const int* in_sizes, int n_in,
                              void* d_out, int out_size){
    const float* src = (const float*)d_in[0];
    const float* tgt = (const float*)d_in[1];
    const float* gen = (const float*)d_in[2];
    float* out = (float*)d_out;

    int dev = 0;
    cudaGetDevice(&dev);
    int sm = 148;
    cudaDeviceGetAttribute(&sm, cudaDevAttrMultiProcessorCount, dev);

    init_kernel<<<32, 256>>>(out);
    dim3 ggrid(IN / BN, IN / BM, 8);
    gemm_exp_kernel<<<ggrid, 256>>>(src, tgt, gen);
    sinkhorn_kernel<<<sm, 512>>>(sm);
    vfin_kernel<<<16, 1024>>>();
    loss_kernel<<<2048, 256>>>(out);
}

// round 4
// speedup vs baseline: 1.6085x; 1.1834x over previous
#include <cuda_runtime.h>
#include <cuda_fp16.h>
#include <cstdint>
#include <cstddef>

#define IN 2048
#define DIM 128
#define NBATCH 4
#define ITERS 50
#define KELEMS (NBATCH*IN*IN)   // 16,777,216 elements

// ---------------- scratch (static device globals: allocation-free) ----------
__device__ __half g_K1[KELEMS];                // K for OT1 (src,tgt)  33.5 MB
__device__ __half g_K2[KELEMS];                // K for OT2 (tgt,gen)  33.5 MB
__device__ float g_A[2][3][NBATCH*IN];         // triple-buffered column accumulators
__device__ float g_u[2][NBATCH*IN];            // final u per OT
__device__ float g_vfin[2][NBATCH*IN];         // final v per OT
__device__ unsigned g_bar4[4 * 32];            // per-segment barrier counters (padded)

// exp(1 - c) for c in [-1,1]; degree-9 Taylor of exp(t), t=-c, times e.
__device__ __forceinline__ float exp_shift(float c){
    float t = -c;
    float p = 2.7557319e-6f;
    p = fmaf(p, t, 2.4801587e-5f);
    p = fmaf(p, t, 1.9841270e-4f);
    p = fmaf(p, t, 1.3888889e-3f);
    p = fmaf(p, t, 8.3333333e-3f);
    p = fmaf(p, t, 4.1666667e-2f);
    p = fmaf(p, t, 1.6666667e-1f);
    p = fmaf(p, t, 0.5f);
    p = fmaf(p, t, 1.0f);
    p = fmaf(p, t, 1.0f);
    return 2.7182818284f * p;
}

// ---------------- init ------------------------------------------------------
__global__ void init_kernel(float* out){
    int idx = blockIdx.x * blockDim.x + threadIdx.x;
    if (idx == 0) out[0] = 0.0f;
    if (idx < 4 * 32) g_bar4[idx] = 0u;
    if (idx < NBATCH*IN){
        g_A[0][0][idx] = 1.0f;   // epoch 0 reads buf0 => v = ones
        g_A[1][0][idx] = 1.0f;
        g_A[0][1][idx] = 0.0f;   // epoch 0 accumulates into buf1
        g_A[1][1][idx] = 0.0f;
        g_A[0][2][idx] = 0.0f;
        g_A[1][2][idx] = 0.0f;
    }
}

// ---------------- tensor-core GEMM + exp -> fp16 K --------------------------
// C[b][i][o] = q_i . k_o via mma.sync m16n8k16 (fp16 in, fp32 accum).
// Block = 256 thr = 8 warps; tile 128x128; warp = 64x32 (wr 0..1, wc 0..3).
#define SA 72   // smem row stride in halves (144 B = 9 x 16B, odd => ldmatrix conflict-free)

__global__ __launch_bounds__(256) void gemm_exp_hmma(
        const float* __restrict__ src, const float* __restrict__ tgt,
        const float* __restrict__ gen){
    int ot = blockIdx.z >> 2;
    int b  = blockIdx.z & 3;
    const float* q  = (ot ? tgt : src) + (size_t)b * IN * DIM;
    const float* kk = (ot ? gen : tgt) + (size_t)b * IN * DIM;
    __half* Kout    = (ot ? g_K2 : g_K1) + (size_t)b * IN * IN;
    int i0 = blockIdx.y * 128;
    int o0 = blockIdx.x * 128;

    __shared__ __half As[128 * SA];
    __shared__ __half Bs[128 * SA];

    int tid  = threadIdx.x;
    int lane = tid & 31, warp = tid >> 5;
    int wr = warp >> 2, wc = warp & 3;

    float c[4][4][4];
    #pragma unroll
    for (int mi = 0; mi < 4; mi++)
        #pragma unroll
        for (int ni = 0; ni < 4; ni++)
            #pragma unroll
            for (int j = 0; j < 4; j++) c[mi][ni][j] = 0.f;

    for (int dc = 0; dc < DIM; dc += 64){
        // load 128 rows x 64 cols of q and kk, fp32 -> fp16, into smem
        #pragma unroll
        for (int l = 0; l < 8; l++){
            int fidx = tid + 256 * l;       // 0..2047
            int r  = fidx >> 4;
            int f4 = (fidx & 15) << 2;
            float4 va = *(const float4*)(q  + (size_t)(i0 + r) * DIM + dc + f4);
            float4 vb = *(const float4*)(kk + (size_t)(o0 + r) * DIM + dc + f4);
            __half2 a0 = __floats2half2_rn(va.x, va.y);
            __half2 a1 = __floats2half2_rn(va.z, va.w);
            __half2 b0 = __floats2half2_rn(vb.x, vb.y);
            __half2 b1 = __floats2half2_rn(vb.z, vb.w);
            uint2 pa = make_uint2(*(uint32_t*)&a0, *(uint32_t*)&a1);
            uint2 pb = make_uint2(*(uint32_t*)&b0, *(uint32_t*)&b1);
            *(uint2*)&As[r * SA + f4] = pa;
            *(uint2*)&Bs[r * SA + f4] = pb;
        }
        __syncthreads();

        #pragma unroll
        for (int ks = 0; ks < 4; ks++){
            int k0 = ks * 16;
            uint32_t af[4][4], bf[4][2];
            #pragma unroll
            for (int mi = 0; mi < 4; mi++){
                int row = wr * 64 + mi * 16 + (lane & 7) + ((lane >> 3) & 1) * 8;
                int col = k0 + (lane >> 4) * 8;
                uint32_t ad = (uint32_t)__cvta_generic_to_shared(&As[row * SA + col]);
                asm volatile("ldmatrix.sync.aligned.m8n8.x4.shared.b16 {%0,%1,%2,%3}, [%4];"
                    : "=r"(af[mi][0]), "=r"(af[mi][1]), "=r"(af[mi][2]), "=r"(af[mi][3])
                    : "r"(ad));
            }
            #pragma unroll
            for (int ni = 0; ni < 4; ni++){
                int rowb = wc * 32 + ni * 8 + (lane & 7);
                int colb = k0 + ((lane >> 3) & 1) * 8;
                uint32_t ad = (uint32_t)__cvta_generic_to_shared(&Bs[rowb * SA + colb]);
                asm volatile("ldmatrix.sync.aligned.m8n8.x2.shared.b16 {%0,%1}, [%2];"
                    : "=r"(bf[ni][0]), "=r"(bf[ni][1])
                    : "r"(ad));
            }
            #pragma unroll
            for (int mi = 0; mi < 4; mi++)
                #pragma unroll
                for (int ni = 0; ni < 4; ni++){
                    asm volatile(
                        "mma.sync.aligned.m16n8k16.row.col.f32.f16.f16.f32 "
                        "{%0,%1,%2,%3}, {%4,%5,%6,%7}, {%8,%9}, {%0,%1,%2,%3};"
                        : "+f"(c[mi][ni][0]), "+f"(c[mi][ni][1]),
                          "+f"(c[mi][ni][2]), "+f"(c[mi][ni][3])
                        : "r"(af[mi][0]), "r"(af[mi][1]), "r"(af[mi][2]), "r"(af[mi][3]),
                          "r"(bf[ni][0]), "r"(bf[ni][1]));
                }
        }
        __syncthreads();
    }

    // epilogue: exp(1-c), diag = e^-10, write half2 pairs directly
    int rbase = i0 + wr * 64 + (lane >> 2);
    int cbase = o0 + wc * 32 + (lane & 3) * 2;
    #pragma unroll
    for (int mi = 0; mi < 4; mi++){
        #pragma unroll
        for (int ni = 0; ni < 4; ni++){
            int ce = cbase + ni * 8;
            #pragma unroll
            for (int h = 0; h < 2; h++){         // h=0: rows +0 (j0,j1), h=1: rows +8 (j2,j3)
                int re = rbase + mi * 16 + h * 8;
                float fx = (re == ce    ) ? 4.5399930e-5f : exp_shift(c[mi][ni][h*2+0]);
                float fy = (re == ce + 1) ? 4.5399930e-5f : exp_shift(c[mi][ni][h*2+1]);
                *(__half2*)(Kout + (size_t)re * IN + ce) = __floats2half2_rn(fx, fy);
            }
        }
    }
}

// ---------------- persistent fused Sinkhorn (fp16 K, per-segment barriers) --
__global__ __launch_bounds__(512, 1) void sinkhorn_kernel(int nblocks){
    __shared__ __align__(16) __half2 v_sh[IN/2];   // 4 KB
    __shared__ __half2 u_sh[16];
    int tid  = threadIdx.x;
    int lane = tid & 31, warp = tid >> 5;

    int seg = blockIdx.x & 3;                       // batch segment 0..3
    int bis = blockIdx.x >> 2;
    int nbs = (nblocks - seg + 3) >> 2;             // blocks in this segment
    int r0 = (int)(((long)IN * bis) / nbs);
    int r1 = (int)(((long)IN * (bis + 1)) / nbs);
    unsigned* mybar = &g_bar4[seg * 32];

    unsigned barcnt = 0;
    for (int e = 0; e < ITERS; e++){
        for (int ot = 0; ot < 2; ot++){
            const __half* Kb = (ot ? g_K2 : g_K1) + (size_t)seg * IN * IN;
            const float* Ar = &g_A[ot][e % 3][seg * IN];
            float*       Az = &g_A[ot][(e + 2) % 3][seg * IN];
            for (int o = tid; o < IN; o += 512){
                float v = 1.0f / __ldcg(Ar + o);
                ((__half*)v_sh)[o] = __float2half_rn(v);
                Az[o] = 0.0f;                        // idempotent zero for next epoch
            }
            __syncthreads();

            float2 accf0 = make_float2(0.f, 0.f);    // this lane's 4 column sums
            float2 accf1 = make_float2(0.f, 0.f);
            for (int tb = r0; tb < r1; tb += 16){
                int nrow = min(16, r1 - tb);
                // phase A: warp w owns row tb+w: u = 1/(K v) via half2 tree
                if (warp < nrow){
                    int row = tb + warp;
                    const uint4* Kr = (const uint4*)(Kb + (size_t)row * IN);
                    const uint4* V4 = (const uint4*)v_sh;
                    float ax = 0.f, ay = 0.f;
                    #pragma unroll
                    for (int j = 0; j < 8; j++){
                        uint4 kv = Kr[j * 32 + lane];
                        uint4 vv = V4[j * 32 + lane];
                        __half2 p0 = __hmul2(*(__half2*)&kv.x, *(__half2*)&vv.x);
                        __half2 p1 = __hmul2(*(__half2*)&kv.y, *(__half2*)&vv.y);
                        __half2 p2 = __hmul2(*(__half2*)&kv.z, *(__half2*)&vv.z);
                        __half2 p3 = __hmul2(*(__half2*)&kv.w, *(__half2*)&vv.w);
                        __half2 s  = __hadd2(__hadd2(p0, p1), __hadd2(p2, p3));
                        float2 f = __half22float2(s);
                        ax += f.x; ay += f.y;
                    }
                    float dot = ax + ay;
                    #pragma unroll
                    for (int off = 16; off; off >>= 1)
                        dot += __shfl_xor_sync(0xffffffffu, dot, off);
                    float u = 1.0f / dot;
                    if (lane == 0){
                        u_sh[warp] = __half2half2(__float2half_rn(u));
                        g_u[ot][seg * IN + row] = u;
                    }
                }
                __syncthreads();
                // phase B: lane owns 4 columns; rows L1-hot from phase A
                const uint2* Ks = (const uint2*)(Kb + (size_t)tb * IN + warp * 128 + lane * 4);
                __half2 h0 = __float2half2_rn(0.f);
                __half2 h1 = __float2half2_rn(0.f);
                if (nrow == 16){
                    #pragma unroll
                    for (int r = 0; r < 16; r++){
                        uint2 kv = Ks[(size_t)r * (IN/4)];
                        __half2 u2 = u_sh[r];
                        h0 = __hfma2(u2, *(__half2*)&kv.x, h0);
                        h1 = __hfma2(u2, *(__half2*)&kv.y, h1);
                    }
                } else {
                    for (int r = 0; r < nrow; r++){
                        uint2 kv = Ks[(size_t)r * (IN/4)];
                        __half2 u2 = u_sh[r];
                        h0 = __hfma2(u2, *(__half2*)&kv.x, h0);
                        h1 = __hfma2(u2, *(__half2*)&kv.y, h1);
                    }
                }
                float2 f0 = __half22float2(h0);
                float2 f1 = __half22float2(h1);
                accf0.x += f0.x; accf0.y += f0.y;
                accf1.x += f1.x; accf1.y += f1.y;
                __syncthreads();
            }
            // flush column partials
            float* Aw = &g_A[ot][(e + 1) % 3][seg * IN];
            int col = warp * 128 + lane * 4;
            atomicAdd(Aw + col + 0, accf0.x);
            atomicAdd(Aw + col + 1, accf0.y);
            atomicAdd(Aw + col + 2, accf1.x);
            atomicAdd(Aw + col + 3, accf1.y);
            __syncthreads();
        }

        // per-segment grid barrier (37 arrivals instead of 148)
        __threadfence();
        __syncthreads();
        barcnt++;
        if (tid == 0){
            atomicAdd(mybar, 1u);
            volatile unsigned* vb = mybar;
            unsigned target = barcnt * (unsigned)nbs;
            while (*vb < target) { __nanosleep(64); }
        }
        __syncthreads();
    }

    // fused vfin: this segment's columns only (synced by the last seg barrier).
    // Final A for epoch 49 was flushed into buf (49+1)%3 == 2.
    for (int idx = bis * 512 + tid; idx < 2 * IN; idx += nbs * 512){
        int o = idx >> 11;
        int r = seg * IN + (idx & 2047);
        g_vfin[o][r] = 1.0f / __ldcg(&g_A[o][2][r]);
    }
}

// ---------------- loss: mean |u1 K1 v1 - u2 K2 v2| --------------------------
__global__ __launch_bounds__(256) void loss_kernel(float* __restrict__ out){
    const uint4* K1 = (const uint4*)g_K1;
    const uint4* K2 = (const uint4*)g_K2;
    const float4* V1 = (const float4*)g_vfin[0];
    const float4* V2 = (const float4*)g_vfin[1];
    int total = KELEMS / 8;
    float s = 0.f;
    for (int idx = blockIdx.x * blockDim.x + threadIdx.x; idx < total;
         idx += gridDim.x * blockDim.x){
        int o8 = idx & 255;          // uint4 (8 halves) within row
        int t  = idx >> 8;
        int i  = t & 2047;
        int b  = t >> 11;
        int row = b * IN + i;
        float u1 = g_u[0][row], u2 = g_u[1][row];
        uint4 k1 = K1[idx], k2 = K2[idx];
        float4 v1a = V1[b * 512 + o8 * 2], v1b = V1[b * 512 + o8 * 2 + 1];
        float4 v2a = V2[b * 512 + o8 * 2], v2b = V2[b * 512 + o8 * 2 + 1];
        float2 a0 = __half22float2(*(__half2*)&k1.x);
        float2 a1 = __half22float2(*(__half2*)&k1.y);
        float2 a2 = __half22float2(*(__half2*)&k1.z);
        float2 a3 = __half22float2(*(__half2*)&k1.w);
        float2 b0 = __half22float2(*(__half2*)&k2.x);
        float2 b1 = __half22float2(*(__half2*)&k2.y);
        float2 b2 = __half22float2(*(__half2*)&k2.z);
        float2 b3 = __half22float2(*(__half2*)&k2.w);
        s += fabsf(u1 * a0.x * v1a.x - u2 * b0.x * v2a.x);
        s += fabsf(u1 * a0.y * v1a.y - u2 * b0.y * v2a.y);
        s += fabsf(u1 * a1.x * v1a.z - u2 * b1.x * v2a.z);
        s += fabsf(u1 * a1.y * v1a.w - u2 * b1.y * v2a.w);
        s += fabsf(u1 * a2.x * v1b.x - u2 * b2.x * v2b.x);
        s += fabsf(u1 * a2.y * v1b.y - u2 * b2.y * v2b.y);
        s += fabsf(u1 * a3.x * v1b.z - u2 * b3.x * v2b.z);
        s += fabsf(u1 * a3.y * v1b.w - u2 * b3.y * v2b.w);
    }
    __shared__ float red[256];
    red[threadIdx.x] = s;
    __syncthreads();
    for (int st = 128; st; st >>= 1){
        if (threadIdx.x < st) red[threadIdx.x] += red[threadIdx.x + st];
        __syncthreads();
    }
    if (threadIdx.x == 0) atomicAdd(out, red[0] * (1.0f / 16777216.0f));
}

// ---------------- launch ----------------------------------------------------
extern "C" void kernel_launch(void* const* d_in, const int* in_sizes, int n_in,
                              void* d_out, int out_size){
    const float* src = (const float*)d_in[0];
    const float* tgt = (const float*)d_in[1];
    const float* gen = (const float*)d_in[2];
    float* out = (float*)d_out;

    int dev = 0;
    cudaGetDevice(&dev);
    int sm = 148;
    cudaDeviceGetAttribute(&sm, cudaDevAttrMultiProcessorCount, dev);

    init_kernel<<<32, 256>>>(out);
    dim3 ggrid(IN / 128, IN / 128, 8);
    gemm_exp_hmma<<<ggrid, 256>>>(src, tgt, gen);
    sinkhorn_kernel<<<sm, 512>>>(sm);
    loss_kernel<<<2048, 256>>>(out);
}

// round 5
// speedup vs baseline: 1.6916x; 1.0517x over previous
#include <cuda_runtime.h>
#include <cuda_fp16.h>
#include <cstdint>
#include <cstddef>

#define IN 2048
#define DIM 128
#define NBATCH 4
#define ITERS 50
#define KELEMS (NBATCH*IN*IN)   // 16,777,216 elements

#define KSCALE (4.5f/127.0f)    // int8 K quantization scale
#define KRSCALE (127.0f/4.5f)

// ---------------- scratch (static device globals: allocation-free) ----------
__device__ uint4 g_K1q4[KELEMS/16];            // K for OT1, int8 quantized (16.8 MB)
__device__ uint4 g_K2q4[KELEMS/16];            // K for OT2, int8 quantized (16.8 MB)
__device__ float g_A[2][3][NBATCH*IN];         // triple-buffered column accumulators
__device__ float g_u[2][NBATCH*IN];            // final u per OT (fp32)
__device__ float g_vfin[2][NBATCH*IN];         // final v per OT (fp32)
__device__ unsigned g_bar4[4 * 32];            // per-segment barrier counters (padded)

// exp(1 - c) for c in [-1,1]; degree-9 Taylor of exp(t), t=-c, times e.
__device__ __forceinline__ float exp_shift(float c){
    float t = -c;
    float p = 2.7557319e-6f;
    p = fmaf(p, t, 2.4801587e-5f);
    p = fmaf(p, t, 1.9841270e-4f);
    p = fmaf(p, t, 1.3888889e-3f);
    p = fmaf(p, t, 8.3333333e-3f);
    p = fmaf(p, t, 4.1666667e-2f);
    p = fmaf(p, t, 1.6666667e-1f);
    p = fmaf(p, t, 0.5f);
    p = fmaf(p, t, 1.0f);
    p = fmaf(p, t, 1.0f);
    return 2.7182818284f * p;
}

// ---------------- init ------------------------------------------------------
__global__ void init_kernel(float* out){
    int idx = blockIdx.x * blockDim.x + threadIdx.x;
    if (idx == 0) out[0] = 0.0f;
    if (idx < 4 * 32) g_bar4[idx] = 0u;
    if (idx < NBATCH*IN){
        g_A[0][0][idx] = 1.0f;   // epoch 0 reads buf0 => v = ones
        g_A[1][0][idx] = 1.0f;
        g_A[0][1][idx] = 0.0f;   // epoch 0 accumulates into buf1
        g_A[1][1][idx] = 0.0f;
        g_A[0][2][idx] = 0.0f;
        g_A[1][2][idx] = 0.0f;
    }
}

// ---------------- tensor-core GEMM + exp -> int8 K --------------------------
#define SA 72   // smem row stride in halves

__global__ __launch_bounds__(256) void gemm_exp_hmma(
        const float* __restrict__ src, const float* __restrict__ tgt,
        const float* __restrict__ gen){
    int ot = blockIdx.z >> 2;
    int b  = blockIdx.z & 3;
    const float* q  = (ot ? tgt : src) + (size_t)b * IN * DIM;
    const float* kk = (ot ? gen : tgt) + (size_t)b * IN * DIM;
    int8_t* Kout    = (int8_t*)(ot ? g_K2q4 : g_K1q4) + (size_t)b * IN * IN;
    int i0 = blockIdx.y * 128;
    int o0 = blockIdx.x * 128;

    __shared__ __half As[128 * SA];
    __shared__ __half Bs[128 * SA];

    int tid  = threadIdx.x;
    int lane = tid & 31, warp = tid >> 5;
    int wr = warp >> 2, wc = warp & 3;

    float c[4][4][4];
    #pragma unroll
    for (int mi = 0; mi < 4; mi++)
        #pragma unroll
        for (int ni = 0; ni < 4; ni++)
            #pragma unroll
            for (int j = 0; j < 4; j++) c[mi][ni][j] = 0.f;

    for (int dc = 0; dc < DIM; dc += 64){
        #pragma unroll
        for (int l = 0; l < 8; l++){
            int fidx = tid + 256 * l;       // 0..2047
            int r  = fidx >> 4;
            int f4 = (fidx & 15) << 2;
            float4 va = *(const float4*)(q  + (size_t)(i0 + r) * DIM + dc + f4);
            float4 vb = *(const float4*)(kk + (size_t)(o0 + r) * DIM + dc + f4);
            __half2 a0 = __floats2half2_rn(va.x, va.y);
            __half2 a1 = __floats2half2_rn(va.z, va.w);
            __half2 b0 = __floats2half2_rn(vb.x, vb.y);
            __half2 b1 = __floats2half2_rn(vb.z, vb.w);
            uint2 pa = make_uint2(*(uint32_t*)&a0, *(uint32_t*)&a1);
            uint2 pb = make_uint2(*(uint32_t*)&b0, *(uint32_t*)&b1);
            *(uint2*)&As[r * SA + f4] = pa;
            *(uint2*)&Bs[r * SA + f4] = pb;
        }
        __syncthreads();

        #pragma unroll
        for (int ks = 0; ks < 4; ks++){
            int k0 = ks * 16;
            uint32_t af[4][4], bf[4][2];
            #pragma unroll
            for (int mi = 0; mi < 4; mi++){
                int row = wr * 64 + mi * 16 + (lane & 7) + ((lane >> 3) & 1) * 8;
                int col = k0 + (lane >> 4) * 8;
                uint32_t ad = (uint32_t)__cvta_generic_to_shared(&As[row * SA + col]);
                asm volatile("ldmatrix.sync.aligned.m8n8.x4.shared.b16 {%0,%1,%2,%3}, [%4];"
                    : "=r"(af[mi][0]), "=r"(af[mi][1]), "=r"(af[mi][2]), "=r"(af[mi][3])
                    : "r"(ad));
            }
            #pragma unroll
            for (int ni = 0; ni < 4; ni++){
                int rowb = wc * 32 + ni * 8 + (lane & 7);
                int colb = k0 + ((lane >> 3) & 1) * 8;
                uint32_t ad = (uint32_t)__cvta_generic_to_shared(&Bs[rowb * SA + colb]);
                asm volatile("ldmatrix.sync.aligned.m8n8.x2.shared.b16 {%0,%1}, [%2];"
                    : "=r"(bf[ni][0]), "=r"(bf[ni][1])
                    : "r"(ad));
            }
            #pragma unroll
            for (int mi = 0; mi < 4; mi++)
                #pragma unroll
                for (int ni = 0; ni < 4; ni++){
                    asm volatile(
                        "mma.sync.aligned.m16n8k16.row.col.f32.f16.f16.f32 "
                        "{%0,%1,%2,%3}, {%4,%5,%6,%7}, {%8,%9}, {%0,%1,%2,%3};"
                        : "+f"(c[mi][ni][0]), "+f"(c[mi][ni][1]),
                          "+f"(c[mi][ni][2]), "+f"(c[mi][ni][3])
                        : "r"(af[mi][0]), "r"(af[mi][1]), "r"(af[mi][2]), "r"(af[mi][3]),
                          "r"(bf[ni][0]), "r"(bf[ni][1]));
                }
        }
        __syncthreads();
    }

    // epilogue: q = round(exp(1-c) * 127/4.5), diag -> 0; pack 4 cols per uint
    int rbase = i0 + wr * 64 + (lane >> 2);
    int cbase = o0 + wc * 32 + (lane & 3) * 2;
    #pragma unroll
    for (int mi = 0; mi < 4; mi++){
        #pragma unroll
        for (int ni = 0; ni < 4; ni++){
            int ce = cbase + ni * 8;
            #pragma unroll
            for (int h = 0; h < 2; h++){
                int re = rbase + mi * 16 + h * 8;
                float fx = (re == ce    ) ? 0.0f : exp_shift(c[mi][ni][h*2+0]);
                float fy = (re == ce + 1) ? 0.0f : exp_shift(c[mi][ni][h*2+1]);
                int qx = __float2int_rn(fminf(fx * KRSCALE, 127.f));
                int qy = __float2int_rn(fminf(fy * KRSCALE, 127.f));
                uint32_t val = (uint32_t)(qx & 0xff) | ((uint32_t)(qy & 0xff) << 8);
                uint32_t other = __shfl_xor_sync(0xffffffffu, val, 1);
                if ((lane & 1) == 0){
                    uint32_t packed = val | (other << 16);
                    *(uint32_t*)(Kout + (size_t)re * IN + ce) = packed;
                }
            }
        }
    }
}

// ---------------- persistent fused Sinkhorn (int8 K, dp4a) ------------------
__global__ __launch_bounds__(512, 1) void sinkhorn_kernel(int nblocks){
    __shared__ __align__(16) float v_f[IN];        // 8 KB, v in fp32
    __shared__ __align__(16) unsigned v_q[IN/4];   // 2 KB, v quantized int8
    __shared__ float u_shf[16];
    __shared__ unsigned u_q4[4];
    __shared__ float ts_sh;                        // tile scale = su * sK
    __shared__ float red[16];
    __shared__ float sc_sh[2];                     // [0]=svk (sK*sv), [1]=rsv (127/vmax)

    int tid  = threadIdx.x;
    int lane = tid & 31, warp = tid >> 5;

    int seg = blockIdx.x & 3;                       // batch segment 0..3
    int bis = blockIdx.x >> 2;
    int nbs = (nblocks - seg + 3) >> 2;             // blocks in this segment
    int r0 = (int)(((long)IN * bis) / nbs);
    int r1 = (int)(((long)IN * (bis + 1)) / nbs);
    unsigned* mybar = &g_bar4[seg * 32];

    unsigned barcnt = 0;
    for (int e = 0; e < ITERS; e++){
        for (int ot = 0; ot < 2; ot++){
            const int8_t* Kq = (const int8_t*)(ot ? g_K2q4 : g_K1q4) + (size_t)seg * IN * IN;
            const float* Ar = &g_A[ot][e % 3][seg * IN];
            float*       Az = &g_A[ot][(e + 2) % 3][seg * IN];

            // ---- v setup: v = 1/A, find vmax, quantize to int8 ----
            float vmax = 0.f;
            for (int o = tid; o < IN; o += 512){
                float v = 1.0f / __ldcg(Ar + o);
                v_f[o] = v;
                vmax = fmaxf(vmax, v);
                Az[o] = 0.0f;
            }
            #pragma unroll
            for (int off = 16; off; off >>= 1)
                vmax = fmaxf(vmax, __shfl_xor_sync(0xffffffffu, vmax, off));
            if (lane == 0) red[warp] = vmax;
            __syncthreads();
            if (warp == 0){
                float m = (lane < 16) ? red[lane] : 0.f;
                #pragma unroll
                for (int off = 16; off; off >>= 1)
                    m = fmaxf(m, __shfl_xor_sync(0xffffffffu, m, off));
                if (lane == 0){
                    sc_sh[0] = (m * (1.0f/127.0f)) * KSCALE;   // svk
                    sc_sh[1] = 127.0f / m;                      // rsv
                }
            }
            __syncthreads();
            float rsv = sc_sh[1];
            {   // 512 threads, 512 uints: each packs 4 bytes
                int o4 = tid;
                int q0 = __float2int_rn(v_f[o4*4+0] * rsv);
                int q1 = __float2int_rn(v_f[o4*4+1] * rsv);
                int q2 = __float2int_rn(v_f[o4*4+2] * rsv);
                int q3 = __float2int_rn(v_f[o4*4+3] * rsv);
                v_q[o4] = (unsigned)(q0 & 0xff) | ((unsigned)(q1 & 0xff) << 8)
                        | ((unsigned)(q2 & 0xff) << 16) | ((unsigned)(q3 & 0xff) << 24);
            }
            __syncthreads();
            float svk = sc_sh[0];

            float accf0 = 0.f, accf1 = 0.f, accf2 = 0.f, accf3 = 0.f;
            for (int tb = r0; tb < r1; tb += 16){
                int nrow = min(16, r1 - tb);
                // ---- phase A: warp w -> row tb+w, exact int dot via dp4a ----
                if (warp < nrow){
                    int row = tb + warp;
                    const uint4* Kr = (const uint4*)(Kq + (size_t)row * IN);
                    const uint4* V4 = (const uint4*)v_q;
                    int id = 0;
                    #pragma unroll
                    for (int j = 0; j < 4; j++){
                        uint4 kb = Kr[j * 32 + lane];
                        uint4 vb = V4[j * 32 + lane];
                        id = __dp4a((int)kb.x, (int)vb.x, id);
                        id = __dp4a((int)kb.y, (int)vb.y, id);
                        id = __dp4a((int)kb.z, (int)vb.z, id);
                        id = __dp4a((int)kb.w, (int)vb.w, id);
                    }
                    #pragma unroll
                    for (int off = 16; off; off >>= 1)
                        id += __shfl_xor_sync(0xffffffffu, id, off);
                    float u = 1.0f / ((float)id * svk);
                    if (lane == 0){
                        u_shf[warp] = u;
                        g_u[ot][seg * IN + row] = u;
                    }
                }
                __syncthreads();
                // ---- warp0: quantize + pack u for this tile ----
                if (warp == 0){
                    float uu = (lane < nrow) ? u_shf[lane] : 0.f;
                    float m = uu;
                    #pragma unroll
                    for (int off = 16; off; off >>= 1)
                        m = fmaxf(m, __shfl_xor_sync(0xffffffffu, m, off));
                    float rsu = 127.0f / m;
                    int qv = __float2int_rn(uu * rsu);
                    int q1 = __shfl_down_sync(0xffffffffu, qv, 1);
                    int q2 = __shfl_down_sync(0xffffffffu, qv, 2);
                    int q3 = __shfl_down_sync(0xffffffffu, qv, 3);
                    if ((lane & 3) == 0 && lane < 16)
                        u_q4[lane >> 2] = (unsigned)(qv & 0xff) | ((unsigned)(q1 & 0xff) << 8)
                                        | ((unsigned)(q2 & 0xff) << 16) | ((unsigned)(q3 & 0xff) << 24);
                    if (lane == 0) ts_sh = m * (KSCALE / 127.0f);
                }
                __syncthreads();
                // ---- phase B: lane owns 4 cols; 4x4 byte transpose + dp4a ----
                const unsigned* Kc = (const unsigned*)(Kq + (size_t)tb * IN) + warp * 32 + lane;
                int ic0 = 0, ic1 = 0, ic2 = 0, ic3 = 0;
                unsigned uqa0 = u_q4[0], uqa1 = u_q4[1], uqa2 = u_q4[2], uqa3 = u_q4[3];
                if (nrow == 16){
                    #pragma unroll
                    for (int g = 0; g < 4; g++){
                        unsigned w0 = Kc[(size_t)(4*g+0) * (IN/4)];
                        unsigned w1 = Kc[(size_t)(4*g+1) * (IN/4)];
                        unsigned w2 = Kc[(size_t)(4*g+2) * (IN/4)];
                        unsigned w3 = Kc[(size_t)(4*g+3) * (IN/4)];
                        unsigned x  = __byte_perm(w0, w1, 0x5140);
                        unsigned y  = __byte_perm(w2, w3, 0x5140);
                        unsigned x2 = __byte_perm(w0, w1, 0x7362);
                        unsigned y2 = __byte_perm(w2, w3, 0x7362);
                        unsigned c0 = __byte_perm(x,  y,  0x5410);
                        unsigned c1 = __byte_perm(x,  y,  0x7632);
                        unsigned c2 = __byte_perm(x2, y2, 0x5410);
                        unsigned c3 = __byte_perm(x2, y2, 0x7632);
                        unsigned uq = (g == 0) ? uqa0 : (g == 1) ? uqa1 : (g == 2) ? uqa2 : uqa3;
                        ic0 = __dp4a((int)c0, (int)uq, ic0);
                        ic1 = __dp4a((int)c1, (int)uq, ic1);
                        ic2 = __dp4a((int)c2, (int)uq, ic2);
                        ic3 = __dp4a((int)c3, (int)uq, ic3);
                    }
                } else {
                    #pragma unroll
                    for (int g = 0; g < 4; g++){
                        unsigned w0 = (4*g+0 < nrow) ? Kc[(size_t)(4*g+0) * (IN/4)] : 0u;
                        unsigned w1 = (4*g+1 < nrow) ? Kc[(size_t)(4*g+1) * (IN/4)] : 0u;
                        unsigned w2 = (4*g+2 < nrow) ? Kc[(size_t)(4*g+2) * (IN/4)] : 0u;
                        unsigned w3 = (4*g+3 < nrow) ? Kc[(size_t)(4*g+3) * (IN/4)] : 0u;
                        unsigned x  = __byte_perm(w0, w1, 0x5140);
                        unsigned y  = __byte_perm(w2, w3, 0x5140);
                        unsigned x2 = __byte_perm(w0, w1, 0x7362);
                        unsigned y2 = __byte_perm(w2, w3, 0x7362);
                        unsigned c0 = __byte_perm(x,  y,  0x5410);
                        unsigned c1 = __byte_perm(x,  y,  0x7632);
                        unsigned c2 = __byte_perm(x2, y2, 0x5410);
                        unsigned c3 = __byte_perm(x2, y2, 0x7632);
                        unsigned uq = (g == 0) ? uqa0 : (g == 1) ? uqa1 : (g == 2) ? uqa2 : uqa3;
                        ic0 = __dp4a((int)c0, (int)uq, ic0);
                        ic1 = __dp4a((int)c1, (int)uq, ic1);
                        ic2 = __dp4a((int)c2, (int)uq, ic2);
                        ic3 = __dp4a((int)c3, (int)uq, ic3);
                    }
                }
                float ts = ts_sh;
                accf0 = fmaf((float)ic0, ts, accf0);
                accf1 = fmaf((float)ic1, ts, accf1);
                accf2 = fmaf((float)ic2, ts, accf2);
                accf3 = fmaf((float)ic3, ts, accf3);
                __syncthreads();
            }
            // flush column partials
            float* Aw = &g_A[ot][(e + 1) % 3][seg * IN];
            int col = warp * 128 + lane * 4;
            atomicAdd(Aw + col + 0, accf0);
            atomicAdd(Aw + col + 1, accf1);
            atomicAdd(Aw + col + 2, accf2);
            atomicAdd(Aw + col + 3, accf3);
            __syncthreads();
        }

        // per-segment grid barrier
        __threadfence();
        __syncthreads();
        barcnt++;
        if (tid == 0){
            atomicAdd(mybar, 1u);
            volatile unsigned* vb = mybar;
            unsigned target = barcnt * (unsigned)nbs;
            while (*vb < target) { __nanosleep(64); }
        }
        __syncthreads();
    }

    // fused vfin: final A for epoch 49 lives in buf (49+1)%3 == 2
    for (int idx = bis * 512 + tid; idx < 2 * IN; idx += nbs * 512){
        int o = idx >> 11;
        int r = seg * IN + (idx & 2047);
        g_vfin[o][r] = 1.0f / __ldcg(&g_A[o][2][r]);
    }
}

// ---------------- loss: mean |u1 K1 v1 - u2 K2 v2|, int8 K ------------------
__global__ __launch_bounds__(256) void loss_kernel(float* __restrict__ out){
    const uint4* K1 = g_K1q4;
    const uint4* K2 = g_K2q4;
    const float4* V1 = (const float4*)g_vfin[0];
    const float4* V2 = (const float4*)g_vfin[1];
    int total = KELEMS / 16;
    float s = 0.f;
    for (int idx = blockIdx.x * blockDim.x + threadIdx.x; idx < total;
         idx += gridDim.x * blockDim.x){
        int c16 = idx & 127;            // uint4 (16 cols) within row
        int t   = idx >> 7;
        int i   = t & 2047;
        int b   = t >> 11;
        int row = b * IN + i;
        float u1 = g_u[0][row], u2 = g_u[1][row];
        uint4 k1 = K1[idx], k2 = K2[idx];
        #pragma unroll
        for (int w = 0; w < 4; w++){
            unsigned w1 = (w==0)?k1.x:(w==1)?k1.y:(w==2)?k1.z:k1.w;
            unsigned w2 = (w==0)?k2.x:(w==1)?k2.y:(w==2)?k2.z:k2.w;
            float4 v1 = V1[b * 512 + c16 * 4 + w];
            float4 v2 = V2[b * 512 + c16 * 4 + w];
            s += fabsf((float)(int)( w1        & 0xff) * (u1 * v1.x)
                     - (float)(int)( w2        & 0xff) * (u2 * v2.x));
            s += fabsf((float)(int)((w1 >>  8) & 0xff) * (u1 * v1.y)
                     - (float)(int)((w2 >>  8) & 0xff) * (u2 * v2.y));
            s += fabsf((float)(int)((w1 >> 16) & 0xff) * (u1 * v1.z)
                     - (float)(int)((w2 >> 16) & 0xff) * (u2 * v2.z));
            s += fabsf((float)(int)((w1 >> 24) & 0xff) * (u1 * v1.w)
                     - (float)(int)((w2 >> 24) & 0xff) * (u2 * v2.w));
        }
    }
    __shared__ float red[256];
    red[threadIdx.x] = s;
    __syncthreads();
    for (int st = 128; st; st >>= 1){
        if (threadIdx.x < st) red[threadIdx.x] += red[threadIdx.x + st];
        __syncthreads();
    }
    if (threadIdx.x == 0) atomicAdd(out, red[0] * (KSCALE / 16777216.0f));
}

// ---------------- launch ----------------------------------------------------
extern "C" void kernel_launch(void* const* d_in, const int* in_sizes, int n_in,
                              void* d_out, int out_size){
    const float* src = (const float*)d_in[0];
    const float* tgt = (const float*)d_in[1];
    const float* gen = (const float*)d_in[2];
    float* out = (float*)d_out;

    int dev = 0;
    cudaGetDevice(&dev);
    int sm = 148;
    cudaDeviceGetAttribute(&sm, cudaDevAttrMultiProcessorCount, dev);

    init_kernel<<<32, 256>>>(out);
    dim3 ggrid(IN / 128, IN / 128, 8);
    gemm_exp_hmma<<<ggrid, 256>>>(src, tgt, gen);
    sinkhorn_kernel<<<sm, 512>>>(sm);
    loss_kernel<<<2048, 256>>>(out);
}

// round 6
// speedup vs baseline: 1.8471x; 1.0919x over previous
#include <cuda_runtime.h>
#include <cuda_fp16.h>
#include <cstdint>
#include <cstddef>

#define IN 2048
#define DIM 128
#define NBATCH 4
#define ITERS 50
#define KELEMS (NBATCH*IN*IN)   // 16,777,216 elements

// ---------------- scratch (static device globals: allocation-free) ----------
__device__ __half g_K1[KELEMS];                // K for OT1 (src,tgt)  33.5 MB
__device__ __half g_K2[KELEMS];                // K for OT2 (tgt,gen)  33.5 MB
__device__ float g_A[2][3][NBATCH*IN];         // triple-buffered column accumulators
__device__ float g_u[2][NBATCH*IN];            // final u per OT
__device__ float g_vfin[2][NBATCH*IN];         // final v per OT
__device__ unsigned g_bar8[8 * 32];            // per-(segment,OT) barrier counters

// exp(1 - c) for c in [-1,1]; degree-9 Taylor of exp(t), t=-c, times e.
__device__ __forceinline__ float exp_shift(float c){
    float t = -c;
    float p = 2.7557319e-6f;
    p = fmaf(p, t, 2.4801587e-5f);
    p = fmaf(p, t, 1.9841270e-4f);
    p = fmaf(p, t, 1.3888889e-3f);
    p = fmaf(p, t, 8.3333333e-3f);
    p = fmaf(p, t, 4.1666667e-2f);
    p = fmaf(p, t, 1.6666667e-1f);
    p = fmaf(p, t, 0.5f);
    p = fmaf(p, t, 1.0f);
    p = fmaf(p, t, 1.0f);
    return 2.7182818284f * p;
}

// ---------------- init ------------------------------------------------------
__global__ void init_kernel(float* out){
    int idx = blockIdx.x * blockDim.x + threadIdx.x;
    if (idx == 0) out[0] = 0.0f;
    if (idx < 8 * 32) g_bar8[idx] = 0u;
    if (idx < NBATCH*IN){
        g_A[0][0][idx] = 1.0f;   // epoch 0 reads buf0 => v = ones
        g_A[1][0][idx] = 1.0f;
        g_A[0][1][idx] = 0.0f;   // epoch 0 accumulates into buf1
        g_A[1][1][idx] = 0.0f;
        g_A[0][2][idx] = 0.0f;
        g_A[1][2][idx] = 0.0f;
    }
}

// ---------------- tensor-core GEMM + exp -> fp16 K --------------------------
#define SA 72   // smem row stride in halves

__global__ __launch_bounds__(256) void gemm_exp_hmma(
        const float* __restrict__ src, const float* __restrict__ tgt,
        const float* __restrict__ gen){
    int ot = blockIdx.z >> 2;
    int b  = blockIdx.z & 3;
    const float* q  = (ot ? tgt : src) + (size_t)b * IN * DIM;
    const float* kk = (ot ? gen : tgt) + (size_t)b * IN * DIM;
    __half* Kout    = (ot ? g_K2 : g_K1) + (size_t)b * IN * IN;
    int i0 = blockIdx.y * 128;
    int o0 = blockIdx.x * 128;

    __shared__ __half As[128 * SA];
    __shared__ __half Bs[128 * SA];

    int tid  = threadIdx.x;
    int lane = tid & 31, warp = tid >> 5;
    int wr = warp >> 2, wc = warp & 3;

    float c[4][4][4];
    #pragma unroll
    for (int mi = 0; mi < 4; mi++)
        #pragma unroll
        for (int ni = 0; ni < 4; ni++)
            #pragma unroll
            for (int j = 0; j < 4; j++) c[mi][ni][j] = 0.f;

    for (int dc = 0; dc < DIM; dc += 64){
        #pragma unroll
        for (int l = 0; l < 8; l++){
            int fidx = tid + 256 * l;       // 0..2047
            int r  = fidx >> 4;
            int f4 = (fidx & 15) << 2;
            float4 va = *(const float4*)(q  + (size_t)(i0 + r) * DIM + dc + f4);
            float4 vb = *(const float4*)(kk + (size_t)(o0 + r) * DIM + dc + f4);
            __half2 a0 = __floats2half2_rn(va.x, va.y);
            __half2 a1 = __floats2half2_rn(va.z, va.w);
            __half2 b0 = __floats2half2_rn(vb.x, vb.y);
            __half2 b1 = __floats2half2_rn(vb.z, vb.w);
            uint2 pa = make_uint2(*(uint32_t*)&a0, *(uint32_t*)&a1);
            uint2 pb = make_uint2(*(uint32_t*)&b0, *(uint32_t*)&b1);
            *(uint2*)&As[r * SA + f4] = pa;
            *(uint2*)&Bs[r * SA + f4] = pb;
        }
        __syncthreads();

        #pragma unroll
        for (int ks = 0; ks < 4; ks++){
            int k0 = ks * 16;
            uint32_t af[4][4], bf[4][2];
            #pragma unroll
            for (int mi = 0; mi < 4; mi++){
                int row = wr * 64 + mi * 16 + (lane & 7) + ((lane >> 3) & 1) * 8;
                int col = k0 + (lane >> 4) * 8;
                uint32_t ad = (uint32_t)__cvta_generic_to_shared(&As[row * SA + col]);
                asm volatile("ldmatrix.sync.aligned.m8n8.x4.shared.b16 {%0,%1,%2,%3}, [%4];"
                    : "=r"(af[mi][0]), "=r"(af[mi][1]), "=r"(af[mi][2]), "=r"(af[mi][3])
                    : "r"(ad));
            }
            #pragma unroll
            for (int ni = 0; ni < 4; ni++){
                int rowb = wc * 32 + ni * 8 + (lane & 7);
                int colb = k0 + ((lane >> 3) & 1) * 8;
                uint32_t ad = (uint32_t)__cvta_generic_to_shared(&Bs[rowb * SA + colb]);
                asm volatile("ldmatrix.sync.aligned.m8n8.x2.shared.b16 {%0,%1}, [%2];"
                    : "=r"(bf[ni][0]), "=r"(bf[ni][1])
                    : "r"(ad));
            }
            #pragma unroll
            for (int mi = 0; mi < 4; mi++)
                #pragma unroll
                for (int ni = 0; ni < 4; ni++){
                    asm volatile(
                        "mma.sync.aligned.m16n8k16.row.col.f32.f16.f16.f32 "
                        "{%0,%1,%2,%3}, {%4,%5,%6,%7}, {%8,%9}, {%0,%1,%2,%3};"
                        : "+f"(c[mi][ni][0]), "+f"(c[mi][ni][1]),
                          "+f"(c[mi][ni][2]), "+f"(c[mi][ni][3])
                        : "r"(af[mi][0]), "r"(af[mi][1]), "r"(af[mi][2]), "r"(af[mi][3]),
                          "r"(bf[ni][0]), "r"(bf[ni][1]));
                }
        }
        __syncthreads();
    }

    // epilogue: exp(1-c), diag = e^-10, write half2 pairs directly
    int rbase = i0 + wr * 64 + (lane >> 2);
    int cbase = o0 + wc * 32 + (lane & 3) * 2;
    #pragma unroll
    for (int mi = 0; mi < 4; mi++){
        #pragma unroll
        for (int ni = 0; ni < 4; ni++){
            int ce = cbase + ni * 8;
            #pragma unroll
            for (int h = 0; h < 2; h++){
                int re = rbase + mi * 16 + h * 8;
                float fx = (re == ce    ) ? 4.5399930e-5f : exp_shift(c[mi][ni][h*2+0]);
                float fy = (re == ce + 1) ? 4.5399930e-5f : exp_shift(c[mi][ni][h*2+1]);
                *(__half2*)(Kout + (size_t)re * IN + ce) = __floats2half2_rn(fx, fy);
            }
        }
    }
}

// ---------------- persistent fused Sinkhorn ---------------------------------
// fp16 K; per-(segment,OT) SPLIT arrive/wait barriers: arrive after OT1 flush,
// do OT2's whole epoch, wait for OT1 only at the top of the next epoch.
// Per OT: [wait] -> v-setup -> sync -> phase A (ALL rows, pairs for MLP) ->
// sync -> phase B (ALL rows, no syncs) -> flush -> fence+sync -> arrive.
__global__ __launch_bounds__(512, 1) void sinkhorn_kernel(int nblocks){
    __shared__ __align__(16) __half2 v_sh[IN/2];   // 4 KB
    __shared__ __half u_h[64];                      // u for all block rows
    int tid  = threadIdx.x;
    int lane = tid & 31, warp = tid >> 5;

    int seg = blockIdx.x & 3;                       // batch segment 0..3
    int bis = blockIdx.x >> 2;
    int nbs = (nblocks - seg + 3) >> 2;             // blocks in this segment
    int r0 = (int)(((long)IN * bis) / nbs);
    int r1 = (int)(((long)IN * (bis + 1)) / nbs);

    for (int e = 0; e < ITERS; e++){
        for (int ot = 0; ot < 2; ot++){
            unsigned* mybar = &g_bar8[(seg * 2 + ot) * 32];
            // wait for ALL blocks to have flushed epoch e-1 of this OT
            if (e > 0){
                if (tid == 0){
                    volatile unsigned* vb = mybar;
                    unsigned target = (unsigned)e * (unsigned)nbs;
                    while (*vb < target) { __nanosleep(32); }
                }
                __syncthreads();
            }
            const __half* Kb = (ot ? g_K2 : g_K1) + (size_t)seg * IN * IN;
            const float* Ar = &g_A[ot][e % 3][seg * IN];
            float*       Az = &g_A[ot][(e + 2) % 3][seg * IN];
            for (int o = tid; o < IN; o += 512){
                float v = 1.0f / __ldcg(Ar + o);
                ((__half*)v_sh)[o] = __float2half_rn(v);
                Az[o] = 0.0f;                        // idempotent zero for next epoch
            }
            __syncthreads();

            // ---- phase A: all rows, processed in pairs for 2x MLP ----
            {
                const uint4* V4 = (const uint4*)v_sh;
                for (int row = r0 + warp; row < r1; row += 32){
                    int rowB = row + 16;
                    bool hasB = rowB < r1;
                    const uint4* Kr  = (const uint4*)(Kb + (size_t)row  * IN);
                    const uint4* KrB = (const uint4*)(Kb + (size_t)(hasB ? rowB : row) * IN);
                    float ax = 0.f, ay = 0.f, bx = 0.f, by = 0.f;
                    #pragma unroll
                    for (int j = 0; j < 8; j++){
                        uint4 vv = V4[j * 32 + lane];
                        uint4 ka = Kr [j * 32 + lane];
                        uint4 kb = KrB[j * 32 + lane];
                        __half2 sa = __hadd2(
                            __hadd2(__hmul2(*(__half2*)&ka.x, *(__half2*)&vv.x),
                                    __hmul2(*(__half2*)&ka.y, *(__half2*)&vv.y)),
                            __hadd2(__hmul2(*(__half2*)&ka.z, *(__half2*)&vv.z),
                                    __hmul2(*(__half2*)&ka.w, *(__half2*)&vv.w)));
                        __half2 sb = __hadd2(
                            __hadd2(__hmul2(*(__half2*)&kb.x, *(__half2*)&vv.x),
                                    __hmul2(*(__half2*)&kb.y, *(__half2*)&vv.y)),
                            __hadd2(__hmul2(*(__half2*)&kb.z, *(__half2*)&vv.z),
                                    __hmul2(*(__half2*)&kb.w, *(__half2*)&vv.w)));
                        float2 fa = __half22float2(sa);
                        float2 fb = __half22float2(sb);
                        ax += fa.x; ay += fa.y;
                        bx += fb.x; by += fb.y;
                    }
                    float dotA = ax + ay;
                    float dotB = bx + by;
                    #pragma unroll
                    for (int off = 16; off; off >>= 1){
                        dotA += __shfl_xor_sync(0xffffffffu, dotA, off);
                        dotB += __shfl_xor_sync(0xffffffffu, dotB, off);
                    }
                    if (lane == 0){
                        float uA = 1.0f / dotA;
                        g_u[ot][seg * IN + row] = uA;
                        u_h[row - r0] = __float2half_rn(uA);
                        if (hasB){
                            float uB = 1.0f / dotB;
                            g_u[ot][seg * IN + rowB] = uB;
                            u_h[rowB - r0] = __float2half_rn(uB);
                        }
                    }
                }
            }
            __syncthreads();

            // ---- phase B: all rows, no intermediate syncs ----
            float2 accf0 = make_float2(0.f, 0.f);
            float2 accf1 = make_float2(0.f, 0.f);
            {
                const __half* Kcol = Kb + warp * 128 + lane * 4;
                for (int base = r0; base < r1; base += 16){
                    int nrow = min(16, r1 - base);
                    __half2 h0 = __float2half2_rn(0.f);
                    __half2 h1 = __float2half2_rn(0.f);
                    if (nrow == 16){
                        #pragma unroll
                        for (int r = 0; r < 16; r++){
                            uint2 kv = *(const uint2*)(Kcol + (size_t)(base + r) * IN);
                            __half2 u2 = __half2half2(u_h[base - r0 + r]);
                            h0 = __hfma2(u2, *(__half2*)&kv.x, h0);
                            h1 = __hfma2(u2, *(__half2*)&kv.y, h1);
                        }
                    } else {
                        for (int r = 0; r < nrow; r++){
                            uint2 kv = *(const uint2*)(Kcol + (size_t)(base + r) * IN);
                            __half2 u2 = __half2half2(u_h[base - r0 + r]);
                            h0 = __hfma2(u2, *(__half2*)&kv.x, h0);
                            h1 = __hfma2(u2, *(__half2*)&kv.y, h1);
                        }
                    }
                    float2 f0 = __half22float2(h0);
                    float2 f1 = __half22float2(h1);
                    accf0.x += f0.x; accf0.y += f0.y;
                    accf1.x += f1.x; accf1.y += f1.y;
                }
            }
            // flush column partials
            float* Aw = &g_A[ot][(e + 1) % 3][seg * IN];
            int col = warp * 128 + lane * 4;
            atomicAdd(Aw + col + 0, accf0.x);
            atomicAdd(Aw + col + 1, accf0.y);
            atomicAdd(Aw + col + 2, accf1.x);
            atomicAdd(Aw + col + 3, accf1.y);

            // arrive (no wait): wait happens at top of next epoch for this OT
            __threadfence();
            __syncthreads();
            if (tid == 0) atomicAdd(mybar, 1u);
        }
    }

    // wait for both OT barriers to fully drain, then fused vfin
    if (tid == 0){
        volatile unsigned* v1 = &g_bar8[(seg * 2 + 0) * 32];
        volatile unsigned* v2 = &g_bar8[(seg * 2 + 1) * 32];
        unsigned target = (unsigned)ITERS * (unsigned)nbs;
        while (*v1 < target) { __nanosleep(32); }
        while (*v2 < target) { __nanosleep(32); }
    }
    __syncthreads();
    // final A for epoch 49 lives in buf (49+1)%3 == 2
    for (int idx = bis * 512 + tid; idx < 2 * IN; idx += nbs * 512){
        int o = idx >> 11;
        int r = seg * IN + (idx & 2047);
        g_vfin[o][r] = 1.0f / __ldcg(&g_A[o][2][r]);
    }
}

// ---------------- loss: mean |u1 K1 v1 - u2 K2 v2| --------------------------
__global__ __launch_bounds__(256) void loss_kernel(float* __restrict__ out){
    const uint4* K1 = (const uint4*)g_K1;
    const uint4* K2 = (const uint4*)g_K2;
    const float4* V1 = (const float4*)g_vfin[0];
    const float4* V2 = (const float4*)g_vfin[1];
    int total = KELEMS / 8;
    float s = 0.f;
    for (int idx = blockIdx.x * blockDim.x + threadIdx.x; idx < total;
         idx += gridDim.x * blockDim.x){
        int o8 = idx & 255;          // uint4 (8 halves) within row
        int t  = idx >> 8;
        int i  = t & 2047;
        int b  = t >> 11;
        int row = b * IN + i;
        float u1 = g_u[0][row], u2 = g_u[1][row];
        uint4 k1 = K1[idx], k2 = K2[idx];
        float4 v1a = V1[b * 512 + o8 * 2], v1b = V1[b * 512 + o8 * 2 + 1];
        float4 v2a = V2[b * 512 + o8 * 2], v2b = V2[b * 512 + o8 * 2 + 1];
        float2 a0 = __half22float2(*(__half2*)&k1.x);
        float2 a1 = __half22float2(*(__half2*)&k1.y);
        float2 a2 = __half22float2(*(__half2*)&k1.z);
        float2 a3 = __half22float2(*(__half2*)&k1.w);
        float2 b0 = __half22float2(*(__half2*)&k2.x);
        float2 b1 = __half22float2(*(__half2*)&k2.y);
        float2 b2 = __half22float2(*(__half2*)&k2.z);
        float2 b3 = __half22float2(*(__half2*)&k2.w);
        s += fabsf(u1 * a0.x * v1a.x - u2 * b0.x * v2a.x);
        s += fabsf(u1 * a0.y * v1a.y - u2 * b0.y * v2a.y);
        s += fabsf(u1 * a1.x * v1a.z - u2 * b1.x * v2a.z);
        s += fabsf(u1 * a1.y * v1a.w - u2 * b1.y * v2a.w);
        s += fabsf(u1 * a2.x * v1b.x - u2 * b2.x * v2b.x);
        s += fabsf(u1 * a2.y * v1b.y - u2 * b2.y * v2b.y);
        s += fabsf(u1 * a3.x * v1b.z - u2 * b3.x * v2b.z);
        s += fabsf(u1 * a3.y * v1b.w - u2 * b3.y * v2b.w);
    }
    __shared__ float red[256];
    red[threadIdx.x] = s;
    __syncthreads();
    for (int st = 128; st; st >>= 1){
        if (threadIdx.x < st) red[threadIdx.x] += red[threadIdx.x + st];
        __syncthreads();
    }
    if (threadIdx.x == 0) atomicAdd(out, red[0] * (1.0f / 16777216.0f));
}

// ---------------- launch ----------------------------------------------------
extern "C" void kernel_launch(void* const* d_in, const int* in_sizes, int n_in,
                              void* d_out, int out_size){
    const float* src = (const float*)d_in[0];
    const float* tgt = (const float*)d_in[1];
    const float* gen = (const float*)d_in[2];
    float* out = (float*)d_out;

    int dev = 0;
    cudaGetDevice(&dev);
    int sm = 148;
    cudaDeviceGetAttribute(&sm, cudaDevAttrMultiProcessorCount, dev);

    init_kernel<<<32, 256>>>(out);
    dim3 ggrid(IN / 128, IN / 128, 8);
    gemm_exp_hmma<<<ggrid, 256>>>(src, tgt, gen);
    sinkhorn_kernel<<<sm, 512>>>(sm);
    loss_kernel<<<2048, 256>>>(out);
}

// round 7
// speedup vs baseline: 2.0055x; 1.0857x over previous
#include <cuda_runtime.h>
#include <cuda_fp16.h>
#include <cstdint>
#include <cstddef>

#define IN 2048
#define DIM 128
#define NBATCH 4
#define ITERS 50
#define KELEMS (NBATCH*IN*IN)   // 16,777,216 elements

// dynamic smem: v (4KB) + per-warp column partials (16 x 2048 halves = 64KB)
#define SMEM_V_BYTES 4096
#define SMEM_TOTAL_BYTES (SMEM_V_BYTES + 16 * IN * 2)

// ---------------- scratch (static device globals: allocation-free) ----------
__device__ __half g_K1[KELEMS];                // K for OT1 (src,tgt)  33.5 MB
__device__ __half g_K2[KELEMS];                // K for OT2 (tgt,gen)  33.5 MB
__device__ float g_A[2][3][NBATCH*IN];         // triple-buffered column accumulators
__device__ float g_u[2][NBATCH*IN];            // final u per OT
__device__ float g_vfin[2][NBATCH*IN];         // final v per OT
__device__ unsigned g_bar8[8 * 32];            // per-(segment,OT) barrier counters

// exp(1 - c) for c in [-1,1]; degree-9 Taylor of exp(t), t=-c, times e.
__device__ __forceinline__ float exp_shift(float c){
    float t = -c;
    float p = 2.7557319e-6f;
    p = fmaf(p, t, 2.4801587e-5f);
    p = fmaf(p, t, 1.9841270e-4f);
    p = fmaf(p, t, 1.3888889e-3f);
    p = fmaf(p, t, 8.3333333e-3f);
    p = fmaf(p, t, 4.1666667e-2f);
    p = fmaf(p, t, 1.6666667e-1f);
    p = fmaf(p, t, 0.5f);
    p = fmaf(p, t, 1.0f);
    p = fmaf(p, t, 1.0f);
    return 2.7182818284f * p;
}

// ---------------- init ------------------------------------------------------
__global__ void init_kernel(float* out){
    int idx = blockIdx.x * blockDim.x + threadIdx.x;
    if (idx == 0) out[0] = 0.0f;
    if (idx < 8 * 32) g_bar8[idx] = 0u;
    if (idx < NBATCH*IN){
        g_A[0][0][idx] = 1.0f;   // epoch 0 reads buf0 => v = ones
        g_A[1][0][idx] = 1.0f;
        g_A[0][1][idx] = 0.0f;   // epoch 0 accumulates into buf1
        g_A[1][1][idx] = 0.0f;
        g_A[0][2][idx] = 0.0f;
        g_A[1][2][idx] = 0.0f;
    }
}

// ---------------- tensor-core GEMM + exp -> fp16 K --------------------------
#define SA 72   // smem row stride in halves

__global__ __launch_bounds__(256) void gemm_exp_hmma(
        const float* __restrict__ src, const float* __restrict__ tgt,
        const float* __restrict__ gen){
    int ot = blockIdx.z >> 2;
    int b  = blockIdx.z & 3;
    const float* q  = (ot ? tgt : src) + (size_t)b * IN * DIM;
    const float* kk = (ot ? gen : tgt) + (size_t)b * IN * DIM;
    __half* Kout    = (ot ? g_K2 : g_K1) + (size_t)b * IN * IN;
    int i0 = blockIdx.y * 128;
    int o0 = blockIdx.x * 128;

    __shared__ __half As[128 * SA];
    __shared__ __half Bs[128 * SA];

    int tid  = threadIdx.x;
    int lane = tid & 31, warp = tid >> 5;
    int wr = warp >> 2, wc = warp & 3;

    float c[4][4][4];
    #pragma unroll
    for (int mi = 0; mi < 4; mi++)
        #pragma unroll
        for (int ni = 0; ni < 4; ni++)
            #pragma unroll
            for (int j = 0; j < 4; j++) c[mi][ni][j] = 0.f;

    for (int dc = 0; dc < DIM; dc += 64){
        #pragma unroll
        for (int l = 0; l < 8; l++){
            int fidx = tid + 256 * l;       // 0..2047
            int r  = fidx >> 4;
            int f4 = (fidx & 15) << 2;
            float4 va = *(const float4*)(q  + (size_t)(i0 + r) * DIM + dc + f4);
            float4 vb = *(const float4*)(kk + (size_t)(o0 + r) * DIM + dc + f4);
            __half2 a0 = __floats2half2_rn(va.x, va.y);
            __half2 a1 = __floats2half2_rn(va.z, va.w);
            __half2 b0 = __floats2half2_rn(vb.x, vb.y);
            __half2 b1 = __floats2half2_rn(vb.z, vb.w);
            uint2 pa = make_uint2(*(uint32_t*)&a0, *(uint32_t*)&a1);
            uint2 pb = make_uint2(*(uint32_t*)&b0, *(uint32_t*)&b1);
            *(uint2*)&As[r * SA + f4] = pa;
            *(uint2*)&Bs[r * SA + f4] = pb;
        }
        __syncthreads();

        #pragma unroll
        for (int ks = 0; ks < 4; ks++){
            int k0 = ks * 16;
            uint32_t af[4][4], bf[4][2];
            #pragma unroll
            for (int mi = 0; mi < 4; mi++){
                int row = wr * 64 + mi * 16 + (lane & 7) + ((lane >> 3) & 1) * 8;
                int col = k0 + (lane >> 4) * 8;
                uint32_t ad = (uint32_t)__cvta_generic_to_shared(&As[row * SA + col]);
                asm volatile("ldmatrix.sync.aligned.m8n8.x4.shared.b16 {%0,%1,%2,%3}, [%4];"
                    : "=r"(af[mi][0]), "=r"(af[mi][1]), "=r"(af[mi][2]), "=r"(af[mi][3])
                    : "r"(ad));
            }
            #pragma unroll
            for (int ni = 0; ni < 4; ni++){
                int rowb = wc * 32 + ni * 8 + (lane & 7);
                int colb = k0 + ((lane >> 3) & 1) * 8;
                uint32_t ad = (uint32_t)__cvta_generic_to_shared(&Bs[rowb * SA + colb]);
                asm volatile("ldmatrix.sync.aligned.m8n8.x2.shared.b16 {%0,%1}, [%2];"
                    : "=r"(bf[ni][0]), "=r"(bf[ni][1])
                    : "r"(ad));
            }
            #pragma unroll
            for (int mi = 0; mi < 4; mi++)
                #pragma unroll
                for (int ni = 0; ni < 4; ni++){
                    asm volatile(
                        "mma.sync.aligned.m16n8k16.row.col.f32.f16.f16.f32 "
                        "{%0,%1,%2,%3}, {%4,%5,%6,%7}, {%8,%9}, {%0,%1,%2,%3};"
                        : "+f"(c[mi][ni][0]), "+f"(c[mi][ni][1]),
                          "+f"(c[mi][ni][2]), "+f"(c[mi][ni][3])
                        : "r"(af[mi][0]), "r"(af[mi][1]), "r"(af[mi][2]), "r"(af[mi][3]),
                          "r"(bf[ni][0]), "r"(bf[ni][1]));
                }
        }
        __syncthreads();
    }

    // epilogue: exp(1-c), diag = e^-10, write half2 pairs directly
    int rbase = i0 + wr * 64 + (lane >> 2);
    int cbase = o0 + wc * 32 + (lane & 3) * 2;
    #pragma unroll
    for (int mi = 0; mi < 4; mi++){
        #pragma unroll
        for (int ni = 0; ni < 4; ni++){
            int ce = cbase + ni * 8;
            #pragma unroll
            for (int h = 0; h < 2; h++){
                int re = rbase + mi * 16 + h * 8;
                float fx = (re == ce    ) ? 4.5399930e-5f : exp_shift(c[mi][ni][h*2+0]);
                float fy = (re == ce + 1) ? 4.5399930e-5f : exp_shift(c[mi][ni][h*2+1]);
                *(__half2*)(Kout + (size_t)re * IN + ce) = __floats2half2_rn(fx, fy);
            }
        }
    }
}

// ---------------- persistent fused Sinkhorn (single K pass per epoch) -------
// Phase A loads each K row ONCE: computes u = 1/(K v) AND accumulates u*K
// into per-warp half2 register accumulators (K^T u). Cross-warp combine via
// smem partials + tree sum. No phase B, K traffic halved vs R6.
__global__ __launch_bounds__(512, 1) void sinkhorn_kernel(int nblocks){
    extern __shared__ __align__(16) char dynsm[];
    __half2* v_sh = (__half2*)dynsm;                     // 4 KB
    __half*  part = (__half*)(dynsm + SMEM_V_BYTES);     // [16][2048] halves

    int tid  = threadIdx.x;
    int lane = tid & 31, warp = tid >> 5;

    int seg = blockIdx.x & 3;                       // batch segment 0..3
    int bis = blockIdx.x >> 2;
    int nbs = (nblocks - seg + 3) >> 2;             // blocks in this segment
    int r0 = (int)(((long)IN * bis) / nbs);
    int r1 = (int)(((long)IN * (bis + 1)) / nbs);

    for (int e = 0; e < ITERS; e++){
        for (int ot = 0; ot < 2; ot++){
            unsigned* mybar = &g_bar8[(seg * 2 + ot) * 32];
            // wait for ALL blocks to have flushed epoch e-1 of this OT
            if (e > 0){
                if (tid == 0){
                    volatile unsigned* vb = mybar;
                    unsigned target = (unsigned)e * (unsigned)nbs;
                    while (*vb < target) { __nanosleep(32); }
                }
                __syncthreads();
            }
            const __half* Kb = (ot ? g_K2 : g_K1) + (size_t)seg * IN * IN;
            const float* Ar = &g_A[ot][e % 3][seg * IN];
            float*       Az = &g_A[ot][(e + 2) % 3][seg * IN];
            for (int o = tid; o < IN; o += 512){
                float v = 1.0f / __ldcg(Ar + o);
                ((__half*)v_sh)[o] = __float2half_rn(v);
                Az[o] = 0.0f;                        // idempotent zero for next epoch
            }
            __syncthreads();

            // ---- fused pass: per row, dot + immediate u*K accumulation ----
            __half2 acc[32];
            #pragma unroll
            for (int j = 0; j < 32; j++) acc[j] = __float2half2_rn(0.f);
            {
                const uint4* V4 = (const uint4*)v_sh;
                for (int row = r0 + warp; row < r1; row += 16){
                    const uint4* Kr = (const uint4*)(Kb + (size_t)row * IN);
                    uint4 k[8];
                    #pragma unroll
                    for (int j = 0; j < 8; j++) k[j] = Kr[j * 32 + lane];
                    float ax = 0.f, ay = 0.f;
                    #pragma unroll
                    for (int j = 0; j < 8; j++){
                        uint4 vv = V4[j * 32 + lane];
                        __half2 s = __hadd2(
                            __hadd2(__hmul2(*(__half2*)&k[j].x, *(__half2*)&vv.x),
                                    __hmul2(*(__half2*)&k[j].y, *(__half2*)&vv.y)),
                            __hadd2(__hmul2(*(__half2*)&k[j].z, *(__half2*)&vv.z),
                                    __hmul2(*(__half2*)&k[j].w, *(__half2*)&vv.w)));
                        float2 f = __half22float2(s);
                        ax += f.x; ay += f.y;
                    }
                    float dot = ax + ay;
                    #pragma unroll
                    for (int off = 16; off; off >>= 1)
                        dot += __shfl_xor_sync(0xffffffffu, dot, off);
                    float u = 1.0f / dot;            // all lanes have it
                    if (lane == 0) g_u[ot][seg * IN + row] = u;
                    __half2 u2 = __float2half2_rn(u);
                    #pragma unroll
                    for (int j = 0; j < 8; j++){
                        acc[j*4+0] = __hfma2(u2, *(__half2*)&k[j].x, acc[j*4+0]);
                        acc[j*4+1] = __hfma2(u2, *(__half2*)&k[j].y, acc[j*4+1]);
                        acc[j*4+2] = __hfma2(u2, *(__half2*)&k[j].z, acc[j*4+2]);
                        acc[j*4+3] = __hfma2(u2, *(__half2*)&k[j].w, acc[j*4+3]);
                    }
                }
            }
            // ---- write per-warp column partials to smem ----
            #pragma unroll
            for (int j = 0; j < 8; j++){
                uint4 o;
                o.x = *(uint32_t*)&acc[j*4+0];
                o.y = *(uint32_t*)&acc[j*4+1];
                o.z = *(uint32_t*)&acc[j*4+2];
                o.w = *(uint32_t*)&acc[j*4+3];
                *(uint4*)&part[warp * IN + j * 256 + lane * 8] = o;
            }
            __syncthreads();

            // ---- cross-warp tree sum + global flush (4 cols per thread) ----
            {
                int c = tid * 4;
                float s0 = 0.f, s1 = 0.f, s2 = 0.f, s3 = 0.f;
                #pragma unroll
                for (int w = 0; w < 16; w++){
                    uint2 hv = *(const uint2*)&part[w * IN + c];
                    float2 f0 = __half22float2(*(__half2*)&hv.x);
                    float2 f1 = __half22float2(*(__half2*)&hv.y);
                    s0 += f0.x; s1 += f0.y; s2 += f1.x; s3 += f1.y;
                }
                float* Aw = &g_A[ot][(e + 1) % 3][seg * IN];
                atomicAdd(Aw + c + 0, s0);
                atomicAdd(Aw + c + 1, s1);
                atomicAdd(Aw + c + 2, s2);
                atomicAdd(Aw + c + 3, s3);
            }

            // arrive (no wait): wait happens at top of next epoch for this OT
            __threadfence();
            __syncthreads();
            if (tid == 0) atomicAdd(mybar, 1u);
        }
    }

    // wait for both OT barriers to fully drain, then fused vfin
    if (tid == 0){
        volatile unsigned* v1 = &g_bar8[(seg * 2 + 0) * 32];
        volatile unsigned* v2 = &g_bar8[(seg * 2 + 1) * 32];
        unsigned target = (unsigned)ITERS * (unsigned)nbs;
        while (*v1 < target) { __nanosleep(32); }
        while (*v2 < target) { __nanosleep(32); }
    }
    __syncthreads();
    // final A for epoch 49 lives in buf (49+1)%3 == 2
    for (int idx = bis * 512 + tid; idx < 2 * IN; idx += nbs * 512){
        int o = idx >> 11;
        int r = seg * IN + (idx & 2047);
        g_vfin[o][r] = 1.0f / __ldcg(&g_A[o][2][r]);
    }
}

// ---------------- loss: mean |u1 K1 v1 - u2 K2 v2| --------------------------
__global__ __launch_bounds__(256) void loss_kernel(float* __restrict__ out){
    const uint4* K1 = (const uint4*)g_K1;
    const uint4* K2 = (const uint4*)g_K2;
    const float4* V1 = (const float4*)g_vfin[0];
    const float4* V2 = (const float4*)g_vfin[1];
    int total = KELEMS / 8;
    float s = 0.f;
    for (int idx = blockIdx.x * blockDim.x + threadIdx.x; idx < total;
         idx += gridDim.x * blockDim.x){
        int o8 = idx & 255;          // uint4 (8 halves) within row
        int t  = idx >> 8;
        int i  = t & 2047;
        int b  = t >> 11;
        int row = b * IN + i;
        float u1 = g_u[0][row], u2 = g_u[1][row];
        uint4 k1 = K1[idx], k2 = K2[idx];
        float4 v1a = V1[b * 512 + o8 * 2], v1b = V1[b * 512 + o8 * 2 + 1];
        float4 v2a = V2[b * 512 + o8 * 2], v2b = V2[b * 512 + o8 * 2 + 1];
        float2 a0 = __half22float2(*(__half2*)&k1.x);
        float2 a1 = __half22float2(*(__half2*)&k1.y);
        float2 a2 = __half22float2(*(__half2*)&k1.z);
        float2 a3 = __half22float2(*(__half2*)&k1.w);
        float2 b0 = __half22float2(*(__half2*)&k2.x);
        float2 b1 = __half22float2(*(__half2*)&k2.y);
        float2 b2 = __half22float2(*(__half2*)&k2.z);
        float2 b3 = __half22float2(*(__half2*)&k2.w);
        s += fabsf(u1 * a0.x * v1a.x - u2 * b0.x * v2a.x);
        s += fabsf(u1 * a0.y * v1a.y - u2 * b0.y * v2a.y);
        s += fabsf(u1 * a1.x * v1a.z - u2 * b1.x * v2a.z);
        s += fabsf(u1 * a1.y * v1a.w - u2 * b1.y * v2a.w);
        s += fabsf(u1 * a2.x * v1b.x - u2 * b2.x * v2b.x);
        s += fabsf(u1 * a2.y * v1b.y - u2 * b2.y * v2b.y);
        s += fabsf(u1 * a3.x * v1b.z - u2 * b3.x * v2b.z);
        s += fabsf(u1 * a3.y * v1b.w - u2 * b3.y * v2b.w);
    }
    __shared__ float red[256];
    red[threadIdx.x] = s;
    __syncthreads();
    for (int st = 128; st; st >>= 1){
        if (threadIdx.x < st) red[threadIdx.x] += red[threadIdx.x + st];
        __syncthreads();
    }
    if (threadIdx.x == 0) atomicAdd(out, red[0] * (1.0f / 16777216.0f));
}

// ---------------- launch ----------------------------------------------------
extern "C" void kernel_launch(void* const* d_in, const int* in_sizes, int n_in,
                              void* d_out, int out_size){
    const float* src = (const float*)d_in[0];
    const float* tgt = (const float*)d_in[1];
    const float* gen = (const float*)d_in[2];
    float* out = (float*)d_out;

    int dev = 0;
    cudaGetDevice(&dev);
    int sm = 148;
    cudaDeviceGetAttribute(&sm, cudaDevAttrMultiProcessorCount, dev);

    cudaFuncSetAttribute(sinkhorn_kernel,
                         cudaFuncAttributeMaxDynamicSharedMemorySize,
                         SMEM_TOTAL_BYTES);

    init_kernel<<<32, 256>>>(out);
    dim3 ggrid(IN / 128, IN / 128, 8);
    gemm_exp_hmma<<<ggrid, 256>>>(src, tgt, gen);
    sinkhorn_kernel<<<sm, 512, SMEM_TOTAL_BYTES>>>(sm);
    loss_kernel<<<2048, 256>>>(out);
}